// round 11
// baseline (speedup 1.0000x reference)
#include <cuda_runtime.h>
#include <cuda_fp16.h>
#include <cstdint>

#define EPSBN 1e-5f
#define HH 300
#define WW 300
#define HW 90000
#define BB 4

// ===========================================================================
// PTX helpers — baseline instructions only (target is sm_103 without 'a')
// ===========================================================================
__device__ __forceinline__ uint32_t smem_u32(const void* p) {
    uint32_t a;
    asm("{ .reg .u64 t; cvta.to.shared.u64 t, %1; cvt.u32.u64 %0, t; }"
        : "=r"(a) : "l"(p));
    return a;
}
__device__ __forceinline__ void ldsm4(uint32_t* r, uint32_t addr) {
    asm volatile("ldmatrix.sync.aligned.m8n8.x4.shared.b16 {%0,%1,%2,%3}, [%4];"
                 : "=r"(r[0]), "=r"(r[1]), "=r"(r[2]), "=r"(r[3]) : "r"(addr));
}
__device__ __forceinline__ void mma_f16(float* c, const uint32_t* a,
                                        uint32_t b0, uint32_t b1) {
    asm volatile(
        "mma.sync.aligned.m16n8k16.row.col.f32.f16.f16.f32 "
        "{%0,%1,%2,%3}, {%4,%5,%6,%7}, {%8,%9}, {%0,%1,%2,%3};"
        : "+f"(c[0]), "+f"(c[1]), "+f"(c[2]), "+f"(c[3])
        : "r"(a[0]), "r"(a[1]), "r"(a[2]), "r"(a[3]), "r"(b0), "r"(b1));
}
#define CP_ASYNC16(dst, src) \
    asm volatile("cp.async.cg.shared.global [%0], [%1], 16;" :: "r"(dst), "l"(src))
#define CP_COMMIT() asm volatile("cp.async.commit_group;" ::: "memory")
#define CP_WAIT0()  asm volatile("cp.async.wait_group 0;" ::: "memory")

// ===========================================================================
// Device scratch (allocation-guard-safe)
// ===========================================================================
__device__ __half g_tr[(size_t)BB * HW * 64];
__device__ __half g_wimg_sh[36 * 4608];  // trunk: 4 cch x 9 shifts, [64 oc][72]
__device__ __half g_wimg_hm[9 * 4608];
__device__ __half g_wimg_rg[9 * 4608];

// ===========================================================================
// Weight prep: w[oc][ci][3][3] fp32 -> per (cchunk, shift) [64 oc][72] fp16
// ===========================================================================
__global__ void prep_w_kernel(const float* __restrict__ w,
                              __half* __restrict__ dst, int CIN)
{
    int i = blockIdx.x * 256 + threadIdx.x;
    if (i >= 64 * CIN * 9) return;
    int kk = i % 9;
    int ci = (i / 9) % CIN;
    int oc = i / (9 * CIN);
    int cc = ci >> 6, c = ci & 63;
    size_t base = (size_t)(cc * 9 + kk) * 4608;
    dst[base + oc * 72 + c] = __float2half_rn(w[i]);
}

// ===========================================================================
// Trunk: conv3x3 (256->64) + BN + ReLU, single-pass fp16 mma, M=32/warp.
// Reads bev fp32 NCHW directly (fused conversion in halo staging).
// CTA 256 thr (8 warps), tile 16x16 px x 64 oc; warp w = rows 2w, 2w+1.
// Rounds of 3 shifts, double-buffered B; 16 syncs total.
// ===========================================================================
__global__ __launch_bounds__(256, 2) void trunk_kernel(
    const float* __restrict__ bev, const __half* __restrict__ wimg,
    const float* __restrict__ gg, const float* __restrict__ bbp,
    const float* __restrict__ mm, const float* __restrict__ vv,
    __half* __restrict__ outp)
{
    extern __shared__ __align__(16) unsigned char dynsmem[];
    __half* sB = (__half*)dynsmem;                // 2 bufs x 27648 B = 55296
    __half* s_h = (__half*)(dynsmem + 55296);     // 324 px x 72 (46656 B)

    __shared__ float s_scale[64], s_shift[64];
    __shared__ int s_offs[324];

    const int tid = threadIdx.x;
    const int w = tid >> 5, lane = tid & 31;
    const int bx = blockIdx.x * 16, by = blockIdx.y * 16;
    const int b = blockIdx.z;

    if (tid < 64) {
        float sc = gg[tid] * rsqrtf(vv[tid] + EPSBN);
        s_scale[tid] = sc;
        s_shift[tid] = bbp[tid] - mm[tid] * sc;
    }
    // per-pixel gmem offsets for the 18x18 halo (-1 = out of bounds)
    for (int p = tid; p < 324; p += 256) {
        int r = p / 18, col = p % 18;
        int gy = by - 1 + r, gx = bx - 1 + col;
        s_offs[p] = ((unsigned)gy < HH && (unsigned)gx < WW) ? gy * WW + gx : -1;
    }

    const int mA = lane & 15;
    const int kselA = (lane >> 4) * 8;
    const int oclB = (lane & 7) + ((lane >> 4) & 1) * 8;
    const int koffB = (lane & 8) ? 8 : 0;

    const uint32_t sB_u = smem_u32(sB);
    const uint32_t sh_u = smem_u32(s_h);

    float acc0[8][4], acc1[8][4];
#pragma unroll
    for (int i = 0; i < 8; i++)
#pragma unroll
        for (int j = 0; j < 4; j++) { acc0[i][j] = 0.f; acc1[i][j] = 0.f; }

    // prefetch round 0 (shifts 0..2, contiguous 27648 B)
    for (int i = tid; i < 1728; i += 256)
        CP_ASYNC16(sB_u + i * 16, (const char*)wimg + (size_t)i * 16);
    CP_COMMIT();

#pragma unroll 1
    for (int R = 0; R < 12; R++) {
        if (R % 3 == 0) {
            __syncthreads();   // previous halo readers done
            // stage halo for cchunk R/3: fp32 NCHW -> fp16 smem (fused cvt)
            const int cc = R / 3;
            const float* src = bev + ((size_t)b * 256 + cc * 64) * HW;
            int c = 0, pix = tid;
#pragma unroll 1
            for (int it = 0; it < 81; it++) {
                int o = s_offs[pix];
                float v = (o >= 0) ? __ldg(src + (size_t)c * HW + o) : 0.f;
                s_h[pix * 72 + c] = __float2half_rn(v);
                pix += 256;
                if (pix >= 324) { pix -= 324; c++; }
            }
        }
        CP_WAIT0();
        __syncthreads();   // B data + halo visible; buf (R+1)&1 readers done
        if (R + 1 < 12) {
            uint32_t dst = sB_u + (uint32_t)((R + 1) & 1) * 27648;
            const char* src = (const char*)wimg + (size_t)(R + 1) * 27648;
            for (int i = tid; i < 1728; i += 256)
                CP_ASYNC16(dst + i * 16, src + (size_t)i * 16);
            CP_COMMIT();
        }

        const uint32_t bufB = sB_u + (uint32_t)(R & 1) * 27648;
#pragma unroll
        for (int q = 0; q < 3; q++) {
            const int k = (R % 3) * 3 + q;
            const int ky = k / 3, kx = k - 3 * ky;
            const uint32_t aBase = sh_u +
                (uint32_t)((((2 * w + ky) * 18 + mA + kx) * 72 + kselA) * 2);
            const uint32_t bBase = bufB + (uint32_t)q * 9216 +
                (uint32_t)((oclB * 72 + koffB) * 2);
#pragma unroll
            for (int kc = 0; kc < 4; kc++) {
                uint32_t a0[4], a1[4];
                ldsm4(a0, aBase + kc * 32);
                ldsm4(a1, aBase + 2592 + kc * 32);   // next row: +18*72*2 B
#pragma unroll
                for (int ng = 0; ng < 4; ng++) {
                    uint32_t bh[4];
                    ldsm4(bh, bBase + ng * 2304 + kc * 32);
                    mma_f16(acc0[2 * ng + 0], a0, bh[0], bh[1]);
                    mma_f16(acc0[2 * ng + 1], a0, bh[2], bh[3]);
                    mma_f16(acc1[2 * ng + 0], a1, bh[0], bh[1]);
                    mma_f16(acc1[2 * ng + 1], a1, bh[2], bh[3]);
                }
            }
        }
    }

    // BN + ReLU -> NHWC fp16 (2 rows per warp)
#pragma unroll
    for (int rr = 0; rr < 2; rr++) {
        const int y = by + 2 * w + rr;
#pragma unroll
        for (int side = 0; side < 2; side++) {
            int x = bx + (lane >> 2) + side * 8;
            if (y < HH && x < WW) {
                size_t base = ((size_t)b * HW + (size_t)y * WW + x) * 64;
#pragma unroll
                for (int nt = 0; nt < 8; nt++) {
                    int oc0 = nt * 8 + (lane & 3) * 2;
                    float v0 = (rr == 0) ? acc0[nt][side * 2 + 0] : acc1[nt][side * 2 + 0];
                    float v1 = (rr == 0) ? acc0[nt][side * 2 + 1] : acc1[nt][side * 2 + 1];
                    v0 = fmaxf(v0 * s_scale[oc0] + s_shift[oc0], 0.f);
                    v1 = fmaxf(v1 * s_scale[oc0 + 1] + s_shift[oc0 + 1], 0.f);
                    __half2 hp;
                    hp.x = __float2half_rn(v0);
                    hp.y = __float2half_rn(v1);
                    *(__half2*)(outp + base + oc0) = hp;
                }
            }
        }
    }
}

// ===========================================================================
// Fused heads: conv3x3 (64->64) x2 + BN + ReLU + 1x1(+bias) x2 -> d_out.
// ALL 9 shift-pairs resident in smem: one cp.async burst, ONE sync, then
// straight-line mma with zero per-shift syncs.
// ===========================================================================
__global__ __launch_bounds__(256, 1) void heads_kernel(
    const __half* __restrict__ act,
    const __half* __restrict__ wimg_hm, const __half* __restrict__ wimg_rg,
    const float* __restrict__ g1, const float* __restrict__ b1,
    const float* __restrict__ m1, const float* __restrict__ v1,
    const float* __restrict__ g2, const float* __restrict__ b2,
    const float* __restrict__ m2, const float* __restrict__ v2,
    const float* __restrict__ w_hm2, const float* __restrict__ b_hm2,
    const float* __restrict__ w_rg2, const float* __restrict__ b_rg2,
    float* __restrict__ out)
{
    extern __shared__ __align__(16) unsigned char dynsmem[];
    __half* sB = (__half*)dynsmem;                // 9 x (hm 9216 | rg 9216) = 165888 B
    __half* s_h = (__half*)(dynsmem + 165888);    // 324 x 72 (46656 B) -> 212544 total
    float* s_mid = (float*)dynsmem;               // epilogue alias: 256*65*4 = 66560 B

    __shared__ float s_sc1[64], s_sh1[64], s_sc2[64], s_sh2[64];
    __shared__ float s_w2h[3 * 64], s_w2r[8 * 64];
    __shared__ float s_b2h[3], s_b2r[8];

    const int tid = threadIdx.x;
    const int w = tid >> 5, lane = tid & 31;
    const int bx = blockIdx.x * 16, by = blockIdx.y * 16;
    const int b = blockIdx.z;

    if (tid < 64) {
        float sc = g1[tid] * rsqrtf(v1[tid] + EPSBN);
        s_sc1[tid] = sc;
        s_sh1[tid] = b1[tid] - m1[tid] * sc;
        float sc2 = g2[tid] * rsqrtf(v2[tid] + EPSBN);
        s_sc2[tid] = sc2;
        s_sh2[tid] = b2[tid] - m2[tid] * sc2;
    }
    for (int i = tid; i < 192; i += 256) s_w2h[i] = w_hm2[i];
    for (int i = tid; i < 512; i += 256) s_w2r[i] = w_rg2[i];
    if (tid < 3) s_b2h[tid] = b_hm2[tid];
    if (tid < 8) s_b2r[tid] = b_rg2[tid];

    const int mA = lane & 15;
    const int kselA = (lane >> 4) * 8;
    const int oclB = (lane & 7) + ((lane >> 4) & 1) * 8;
    const int koffB = (lane & 8) ? 8 : 0;

    const uint32_t sB_u = smem_u32(sB);
    const uint32_t sh_u = smem_u32(s_h);

    float aH0[8][4], aH1[8][4], aR0[8][4], aR1[8][4];
#pragma unroll
    for (int i = 0; i < 8; i++)
#pragma unroll
        for (int j = 0; j < 4; j++) {
            aH0[i][j] = 0.f; aH1[i][j] = 0.f;
            aR0[i][j] = 0.f; aR1[i][j] = 0.f;
        }

    // one burst: all 9 shifts, both heads (165888 B)
    for (int i = tid; i < 5184; i += 256) {
        int sh = i / 576, j = i - sh * 576;
        uint32_t dst = sB_u + (uint32_t)sh * 18432 + (uint32_t)j * 16;
        CP_ASYNC16(dst, (const char*)wimg_hm + (size_t)i * 16);
        CP_ASYNC16(dst + 9216, (const char*)wimg_rg + (size_t)i * 16);
    }
    CP_COMMIT();

    // stage halo once (CIN = 64): 324 px, 8 uint4 per pixel
    for (int idx = tid; idx < 324 * 8; idx += 256) {
        int pix = idx >> 3, j = idx & 7;
        int r = pix / 18, col = pix % 18;
        int gy = by - 1 + r, gx = bx - 1 + col;
        uint4 v = make_uint4(0, 0, 0, 0);
        if ((unsigned)gy < HH && (unsigned)gx < WW)
            v = ((const uint4*)(act + ((size_t)b * HW + (size_t)gy * WW + gx) * 64))[j];
        ((uint4*)(s_h + pix * 72))[j] = v;
    }

    CP_WAIT0();
    __syncthreads();   // the only pre-epilogue sync

#pragma unroll 1
    for (int k = 0; k < 9; k++) {
        const int ky = k / 3, kx = k - 3 * ky;
        const uint32_t aBase = sh_u +
            (uint32_t)((((2 * w + ky) * 18 + mA + kx) * 72 + kselA) * 2);
        const uint32_t bBaseH = sB_u + (uint32_t)k * 18432 +
            (uint32_t)((oclB * 72 + koffB) * 2);
        const uint32_t bBaseR = bBaseH + 9216;

#pragma unroll
        for (int kc = 0; kc < 4; kc++) {
            uint32_t a0[4], a1[4];
            ldsm4(a0, aBase + kc * 32);
            ldsm4(a1, aBase + 2592 + kc * 32);
#pragma unroll
            for (int ng = 0; ng < 4; ng++) {
                uint32_t bh[4], br[4];
                ldsm4(bh, bBaseH + ng * 2304 + kc * 32);
                ldsm4(br, bBaseR + ng * 2304 + kc * 32);
                mma_f16(aH0[2 * ng + 0], a0, bh[0], bh[1]);
                mma_f16(aH0[2 * ng + 1], a0, bh[2], bh[3]);
                mma_f16(aH1[2 * ng + 0], a1, bh[0], bh[1]);
                mma_f16(aH1[2 * ng + 1], a1, bh[2], bh[3]);
                mma_f16(aR0[2 * ng + 0], a0, br[0], br[1]);
                mma_f16(aR0[2 * ng + 1], a0, br[2], br[3]);
                mma_f16(aR1[2 * ng + 0], a1, br[0], br[1]);
                mma_f16(aR1[2 * ng + 1], a1, br[2], br[3]);
            }
        }
    }
    __syncthreads();   // all weight/halo reads done; safe to alias s_mid

    // ---- epilogue head 1 (heatmap, 3ch) ----
#pragma unroll
    for (int rr = 0; rr < 2; rr++)
#pragma unroll
        for (int side = 0; side < 2; side++) {
            int p = (2 * w + rr) * 16 + (lane >> 2) + side * 8;
            int oc0 = (lane & 3) * 2;
#pragma unroll
            for (int nt = 0; nt < 8; nt++) {
                int oc = nt * 8 + oc0;
                float v0 = (rr == 0) ? aH0[nt][side * 2 + 0] : aH1[nt][side * 2 + 0];
                float v1 = (rr == 0) ? aH0[nt][side * 2 + 1] : aH1[nt][side * 2 + 1];
                s_mid[p * 65 + oc] = fmaxf(v0 * s_sc1[oc] + s_sh1[oc], 0.f);
                s_mid[p * 65 + oc + 1] = fmaxf(v1 * s_sc1[oc + 1] + s_sh1[oc + 1], 0.f);
            }
        }
    __syncthreads();
    {
        int p = tid;
        int yy = by + (p >> 4), xx = bx + (p & 15);
        if (yy < HH && xx < WW) {
            const float* row = s_mid + p * 65;
            float o0 = s_b2h[0], o1 = s_b2h[1], o2 = s_b2h[2];
#pragma unroll 8
            for (int c = 0; c < 64; c++) {
                float a = row[c];
                o0 += a * s_w2h[c];
                o1 += a * s_w2h[64 + c];
                o2 += a * s_w2h[128 + c];
            }
            size_t base = ((size_t)b * 3 * HH + yy) * WW + xx;
            out[base] = o0;
            out[base + (size_t)HW] = o1;
            out[base + (size_t)2 * HW] = o2;
        }
    }
    __syncthreads();

    // ---- epilogue head 2 (box_reg, 8ch) ----
#pragma unroll
    for (int rr = 0; rr < 2; rr++)
#pragma unroll
        for (int side = 0; side < 2; side++) {
            int p = (2 * w + rr) * 16 + (lane >> 2) + side * 8;
            int oc0 = (lane & 3) * 2;
#pragma unroll
            for (int nt = 0; nt < 8; nt++) {
                int oc = nt * 8 + oc0;
                float v0 = (rr == 0) ? aR0[nt][side * 2 + 0] : aR1[nt][side * 2 + 0];
                float v1 = (rr == 0) ? aR0[nt][side * 2 + 1] : aR1[nt][side * 2 + 1];
                s_mid[p * 65 + oc] = fmaxf(v0 * s_sc2[oc] + s_sh2[oc], 0.f);
                s_mid[p * 65 + oc + 1] = fmaxf(v1 * s_sc2[oc + 1] + s_sh2[oc + 1], 0.f);
            }
        }
    __syncthreads();
    {
        int p = tid;
        int yy = by + (p >> 4), xx = bx + (p & 15);
        if (yy < HH && xx < WW) {
            const float* row = s_mid + p * 65;
            float o[8];
#pragma unroll
            for (int n = 0; n < 8; n++) o[n] = s_b2r[n];
#pragma unroll 8
            for (int c = 0; c < 64; c++) {
                float a = row[c];
#pragma unroll
                for (int n = 0; n < 8; n++) o[n] += a * s_w2r[n * 64 + c];
            }
            float* rg = out + (size_t)BB * 3 * HW;
#pragma unroll
            for (int n = 0; n < 8; n++)
                rg[((size_t)(b * 8 + n) * HH + yy) * WW + xx] = o[n];
        }
    }
}

// ===========================================================================
extern "C" void kernel_launch(void* const* d_in, const int* in_sizes, int n_in,
                              void* d_out, int out_size)
{
    const float* bev   = (const float*)d_in[0];
    const float* w_sh  = (const float*)d_in[1];
    const float* g_sh  = (const float*)d_in[2];
    const float* b_sh  = (const float*)d_in[3];
    const float* m_sh  = (const float*)d_in[4];
    const float* v_sh  = (const float*)d_in[5];
    const float* w_hm1 = (const float*)d_in[6];
    const float* g_hm1 = (const float*)d_in[7];
    const float* b_hm1 = (const float*)d_in[8];
    const float* m_hm1 = (const float*)d_in[9];
    const float* v_hm1 = (const float*)d_in[10];
    const float* w_hm2 = (const float*)d_in[11];
    const float* b_hm2 = (const float*)d_in[12];
    const float* w_rg1 = (const float*)d_in[13];
    const float* g_rg1 = (const float*)d_in[14];
    const float* b_rg1 = (const float*)d_in[15];
    const float* m_rg1 = (const float*)d_in[16];
    const float* v_rg1 = (const float*)d_in[17];
    const float* w_rg2 = (const float*)d_in[18];
    const float* b_rg2 = (const float*)d_in[19];

    __half *trh, *wi_sh, *wi_hm, *wi_rg;
    cudaGetSymbolAddress((void**)&trh, g_tr);
    cudaGetSymbolAddress((void**)&wi_sh, g_wimg_sh);
    cudaGetSymbolAddress((void**)&wi_hm, g_wimg_hm);
    cudaGetSymbolAddress((void**)&wi_rg, g_wimg_rg);

    const int DSMEM_T = 55296 + 46656;    // 101952 B (occ 2)
    const int DSMEM_H = 165888 + 46656;   // 212544 B (occ 1)
    cudaFuncSetAttribute(trunk_kernel, cudaFuncAttributeMaxDynamicSharedMemorySize, DSMEM_T);
    cudaFuncSetAttribute(heads_kernel, cudaFuncAttributeMaxDynamicSharedMemorySize, DSMEM_H);

    // 1. weight images
    prep_w_kernel<<<(64 * 256 * 9 + 255) / 256, 256>>>(w_sh, wi_sh, 256);
    prep_w_kernel<<<(64 * 64 * 9 + 255) / 256, 256>>>(w_hm1, wi_hm, 64);
    prep_w_kernel<<<(64 * 64 * 9 + 255) / 256, 256>>>(w_rg1, wi_rg, 64);

    dim3 grid(19, 19, BB);   // 16x16 pixel tiles

    // 2. trunk conv (reads bev fp32 directly) -> NHWC fp16
    trunk_kernel<<<grid, 256, DSMEM_T>>>(bev, wi_sh, g_sh, b_sh, m_sh, v_sh, trh);

    // 3. fused heads -> d_out
    heads_kernel<<<grid, 256, DSMEM_H>>>(
        trh, wi_hm, wi_rg,
        g_hm1, b_hm1, m_hm1, v_hm1,
        g_rg1, b_rg1, m_rg1, v_rg1,
        w_hm2, b_hm2, w_rg2, b_rg2, (float*)d_out);
}

// round 12
// speedup vs baseline: 1.8342x; 1.8342x over previous
#include <cuda_runtime.h>
#include <cuda_fp16.h>
#include <cstdint>

#define EPSBN 1e-5f
#define HH 300
#define WW 300
#define HW 90000
#define BB 4

// ===========================================================================
// PTX helpers — baseline instructions only (target is sm_103 without 'a')
// ===========================================================================
__device__ __forceinline__ uint32_t smem_u32(const void* p) {
    uint32_t a;
    asm("{ .reg .u64 t; cvta.to.shared.u64 t, %1; cvt.u32.u64 %0, t; }"
        : "=r"(a) : "l"(p));
    return a;
}
__device__ __forceinline__ void ldsm4(uint32_t* r, uint32_t addr) {
    asm volatile("ldmatrix.sync.aligned.m8n8.x4.shared.b16 {%0,%1,%2,%3}, [%4];"
                 : "=r"(r[0]), "=r"(r[1]), "=r"(r[2]), "=r"(r[3]) : "r"(addr));
}
__device__ __forceinline__ void mma_f16(float* c, const uint32_t* a,
                                        uint32_t b0, uint32_t b1) {
    asm volatile(
        "mma.sync.aligned.m16n8k16.row.col.f32.f16.f16.f32 "
        "{%0,%1,%2,%3}, {%4,%5,%6,%7}, {%8,%9}, {%0,%1,%2,%3};"
        : "+f"(c[0]), "+f"(c[1]), "+f"(c[2]), "+f"(c[3])
        : "r"(a[0]), "r"(a[1]), "r"(a[2]), "r"(a[3]), "r"(b0), "r"(b1));
}
#define CP_ASYNC16(dst, src) \
    asm volatile("cp.async.cg.shared.global [%0], [%1], 16;" :: "r"(dst), "l"(src))
#define CP_COMMIT() asm volatile("cp.async.commit_group;" ::: "memory")
#define CP_WAIT0()  asm volatile("cp.async.wait_group 0;" ::: "memory")

// ===========================================================================
// Device scratch (allocation-guard-safe)
// ===========================================================================
__device__ __half g_bev[(size_t)BB * HW * 256];
__device__ __half g_tr[(size_t)BB * HW * 64];
__device__ __half g_wimg_sh[36 * 4608];  // trunk: 4 cch x 9 shifts, [64 oc][72]
__device__ __half g_wimg_hm[9 * 4608];
__device__ __half g_wimg_rg[9 * 4608];

// ===========================================================================
// NCHW fp32 -> NHWC fp16 (bev)
// ===========================================================================
__global__ __launch_bounds__(256) void nhwc_kernel(const float* __restrict__ in)
{
    __shared__ float tile[32][33];
    const int tx = threadIdx.x & 31, ty = threadIdx.x >> 5;
    const int w0 = blockIdx.x * 32, c0 = blockIdx.y * 32;
    const int b = blockIdx.z / HH, h = blockIdx.z % HH;
#pragma unroll
    for (int q = 0; q < 4; q++) {
        int c = c0 + ty * 4 + q, w = w0 + tx;
        tile[ty * 4 + q][tx] = (w < WW) ? in[(((size_t)b * 256 + c) * HH + h) * WW + w] : 0.f;
    }
    __syncthreads();
#pragma unroll
    for (int q = 0; q < 4; q++) {
        int w = w0 + ty * 4 + q;
        if (w >= WW) continue;
        size_t o = ((size_t)b * HW + (size_t)h * WW + w) * 256 + c0 + tx;
        g_bev[o] = __float2half_rn(tile[tx][ty * 4 + q]);
    }
}

// ===========================================================================
// Weight prep: w[oc][ci][3][3] fp32 -> per (cchunk, shift) [64 oc][72] fp16
// ===========================================================================
__global__ void prep_w_kernel(const float* __restrict__ w,
                              __half* __restrict__ dst, int CIN)
{
    int i = blockIdx.x * 256 + threadIdx.x;
    if (i >= 64 * CIN * 9) return;
    int kk = i % 9;
    int ci = (i / 9) % CIN;
    int oc = i / (9 * CIN);
    int cc = ci >> 6, c = ci & 63;
    size_t base = (size_t)(cc * 9 + kk) * 4608;
    dst[base + oc * 72 + c] = __float2half_rn(w[i]);
}

// ===========================================================================
// Trunk: conv3x3 (256->64) + BN + ReLU, single-pass fp16 mma, M=32/warp.
// CTA 256 thr (8 warps), tile 16x16 px x 64 oc; warp w = rows 2w, 2w+1.
// Rounds of 3 shifts, double-buffered B; 16 syncs total.
// ===========================================================================
__global__ __launch_bounds__(256, 2) void trunk_kernel(
    const __half* __restrict__ act, const __half* __restrict__ wimg,
    const float* __restrict__ gg, const float* __restrict__ bbp,
    const float* __restrict__ mm, const float* __restrict__ vv,
    __half* __restrict__ outp)
{
    extern __shared__ __align__(16) unsigned char dynsmem[];
    __half* sB = (__half*)dynsmem;                // 2 bufs x 27648 B = 55296
    __half* s_h = (__half*)(dynsmem + 55296);     // 324 px x 72 (46656 B)

    __shared__ float s_scale[64], s_shift[64];

    const int tid = threadIdx.x;
    const int w = tid >> 5, lane = tid & 31;
    const int bx = blockIdx.x * 16, by = blockIdx.y * 16;
    const int b = blockIdx.z;

    if (tid < 64) {
        float sc = gg[tid] * rsqrtf(vv[tid] + EPSBN);
        s_scale[tid] = sc;
        s_shift[tid] = bbp[tid] - mm[tid] * sc;
    }

    const int mA = lane & 15;
    const int kselA = (lane >> 4) * 8;
    const int oclB = (lane & 7) + ((lane >> 4) & 1) * 8;
    const int koffB = (lane & 8) ? 8 : 0;

    const uint32_t sB_u = smem_u32(sB);
    const uint32_t sh_u = smem_u32(s_h);

    float acc0[8][4], acc1[8][4];
#pragma unroll
    for (int i = 0; i < 8; i++)
#pragma unroll
        for (int j = 0; j < 4; j++) { acc0[i][j] = 0.f; acc1[i][j] = 0.f; }

    // prefetch round 0 (shifts 0..2, contiguous 27648 B)
    for (int i = tid; i < 1728; i += 256)
        CP_ASYNC16(sB_u + i * 16, (const char*)wimg + (size_t)i * 16);
    CP_COMMIT();

#pragma unroll 1
    for (int R = 0; R < 12; R++) {
        if (R % 3 == 0) {
            __syncthreads();   // previous halo readers done
            // stage halo for cchunk R/3: 324 px x 64 ch, 8 uint4 per pixel
            const int cc = R / 3;
            for (int idx = tid; idx < 324 * 8; idx += 256) {
                int pix = idx >> 3, j = idx & 7;
                int r = pix / 18, col = pix % 18;
                int gy = by - 1 + r, gx = bx - 1 + col;
                uint4 v = make_uint4(0, 0, 0, 0);
                if ((unsigned)gy < HH && (unsigned)gx < WW)
                    v = ((const uint4*)(act + ((size_t)b * HW + (size_t)gy * WW + gx) * 256 + cc * 64))[j];
                ((uint4*)(s_h + pix * 72))[j] = v;
            }
        }
        CP_WAIT0();
        __syncthreads();   // B data + halo visible; buf (R+1)&1 readers done
        if (R + 1 < 12) {
            uint32_t dst = sB_u + (uint32_t)((R + 1) & 1) * 27648;
            const char* src = (const char*)wimg + (size_t)(R + 1) * 27648;
            for (int i = tid; i < 1728; i += 256)
                CP_ASYNC16(dst + i * 16, src + (size_t)i * 16);
            CP_COMMIT();
        }

        const uint32_t bufB = sB_u + (uint32_t)(R & 1) * 27648;
#pragma unroll
        for (int q = 0; q < 3; q++) {
            const int k = (R % 3) * 3 + q;
            const int ky = k / 3, kx = k - 3 * ky;
            const uint32_t aBase = sh_u +
                (uint32_t)((((2 * w + ky) * 18 + mA + kx) * 72 + kselA) * 2);
            const uint32_t bBase = bufB + (uint32_t)q * 9216 +
                (uint32_t)((oclB * 72 + koffB) * 2);
#pragma unroll
            for (int kc = 0; kc < 4; kc++) {
                uint32_t a0[4], a1[4];
                ldsm4(a0, aBase + kc * 32);
                ldsm4(a1, aBase + 2592 + kc * 32);   // next row: +18*72*2 B
#pragma unroll
                for (int ng = 0; ng < 4; ng++) {
                    uint32_t bh[4];
                    ldsm4(bh, bBase + ng * 2304 + kc * 32);
                    mma_f16(acc0[2 * ng + 0], a0, bh[0], bh[1]);
                    mma_f16(acc0[2 * ng + 1], a0, bh[2], bh[3]);
                    mma_f16(acc1[2 * ng + 0], a1, bh[0], bh[1]);
                    mma_f16(acc1[2 * ng + 1], a1, bh[2], bh[3]);
                }
            }
        }
    }

    // BN + ReLU -> NHWC fp16 (2 rows per warp)
#pragma unroll
    for (int rr = 0; rr < 2; rr++) {
        const int y = by + 2 * w + rr;
#pragma unroll
        for (int side = 0; side < 2; side++) {
            int x = bx + (lane >> 2) + side * 8;
            if (y < HH && x < WW) {
                size_t base = ((size_t)b * HW + (size_t)y * WW + x) * 64;
#pragma unroll
                for (int nt = 0; nt < 8; nt++) {
                    int oc0 = nt * 8 + (lane & 3) * 2;
                    float v0 = (rr == 0) ? acc0[nt][side * 2 + 0] : acc1[nt][side * 2 + 0];
                    float v1 = (rr == 0) ? acc0[nt][side * 2 + 1] : acc1[nt][side * 2 + 1];
                    v0 = fmaxf(v0 * s_scale[oc0] + s_shift[oc0], 0.f);
                    v1 = fmaxf(v1 * s_scale[oc0 + 1] + s_shift[oc0 + 1], 0.f);
                    __half2 hp;
                    hp.x = __float2half_rn(v0);
                    hp.y = __float2half_rn(v1);
                    *(__half2*)(outp + base + oc0) = hp;
                }
            }
        }
    }
}

// ===========================================================================
// Fused heads: conv3x3 (64->64) x2 + BN + ReLU + 1x1(+bias) x2 -> d_out.
// ALL 9 shift-pairs resident in smem: one cp.async burst, ONE sync, then
// straight-line mma with zero per-shift syncs.
// ===========================================================================
__global__ __launch_bounds__(256, 1) void heads_kernel(
    const __half* __restrict__ act,
    const __half* __restrict__ wimg_hm, const __half* __restrict__ wimg_rg,
    const float* __restrict__ g1, const float* __restrict__ b1,
    const float* __restrict__ m1, const float* __restrict__ v1,
    const float* __restrict__ g2, const float* __restrict__ b2,
    const float* __restrict__ m2, const float* __restrict__ v2,
    const float* __restrict__ w_hm2, const float* __restrict__ b_hm2,
    const float* __restrict__ w_rg2, const float* __restrict__ b_rg2,
    float* __restrict__ out)
{
    extern __shared__ __align__(16) unsigned char dynsmem[];
    __half* sB = (__half*)dynsmem;                // 9 x (hm 9216 | rg 9216) = 165888 B
    __half* s_h = (__half*)(dynsmem + 165888);    // 324 x 72 (46656 B) -> 212544 total
    float* s_mid = (float*)dynsmem;               // epilogue alias: 256*65*4 = 66560 B

    __shared__ float s_sc1[64], s_sh1[64], s_sc2[64], s_sh2[64];
    __shared__ float s_w2h[3 * 64], s_w2r[8 * 64];
    __shared__ float s_b2h[3], s_b2r[8];

    const int tid = threadIdx.x;
    const int w = tid >> 5, lane = tid & 31;
    const int bx = blockIdx.x * 16, by = blockIdx.y * 16;
    const int b = blockIdx.z;

    if (tid < 64) {
        float sc = g1[tid] * rsqrtf(v1[tid] + EPSBN);
        s_sc1[tid] = sc;
        s_sh1[tid] = b1[tid] - m1[tid] * sc;
        float sc2 = g2[tid] * rsqrtf(v2[tid] + EPSBN);
        s_sc2[tid] = sc2;
        s_sh2[tid] = b2[tid] - m2[tid] * sc2;
    }
    for (int i = tid; i < 192; i += 256) s_w2h[i] = w_hm2[i];
    for (int i = tid; i < 512; i += 256) s_w2r[i] = w_rg2[i];
    if (tid < 3) s_b2h[tid] = b_hm2[tid];
    if (tid < 8) s_b2r[tid] = b_rg2[tid];

    const int mA = lane & 15;
    const int kselA = (lane >> 4) * 8;
    const int oclB = (lane & 7) + ((lane >> 4) & 1) * 8;
    const int koffB = (lane & 8) ? 8 : 0;

    const uint32_t sB_u = smem_u32(sB);
    const uint32_t sh_u = smem_u32(s_h);

    float aH0[8][4], aH1[8][4], aR0[8][4], aR1[8][4];
#pragma unroll
    for (int i = 0; i < 8; i++)
#pragma unroll
        for (int j = 0; j < 4; j++) {
            aH0[i][j] = 0.f; aH1[i][j] = 0.f;
            aR0[i][j] = 0.f; aR1[i][j] = 0.f;
        }

    // one burst: all 9 shifts, both heads (165888 B)
    for (int i = tid; i < 5184; i += 256) {
        int sh = i / 576, j = i - sh * 576;
        uint32_t dst = sB_u + (uint32_t)sh * 18432 + (uint32_t)j * 16;
        CP_ASYNC16(dst, (const char*)wimg_hm + (size_t)i * 16);
        CP_ASYNC16(dst + 9216, (const char*)wimg_rg + (size_t)i * 16);
    }
    CP_COMMIT();

    // stage halo once (CIN = 64): 324 px, 8 uint4 per pixel
    for (int idx = tid; idx < 324 * 8; idx += 256) {
        int pix = idx >> 3, j = idx & 7;
        int r = pix / 18, col = pix % 18;
        int gy = by - 1 + r, gx = bx - 1 + col;
        uint4 v = make_uint4(0, 0, 0, 0);
        if ((unsigned)gy < HH && (unsigned)gx < WW)
            v = ((const uint4*)(act + ((size_t)b * HW + (size_t)gy * WW + gx) * 64))[j];
        ((uint4*)(s_h + pix * 72))[j] = v;
    }

    CP_WAIT0();
    __syncthreads();   // the only pre-epilogue sync

#pragma unroll 1
    for (int k = 0; k < 9; k++) {
        const int ky = k / 3, kx = k - 3 * ky;
        const uint32_t aBase = sh_u +
            (uint32_t)((((2 * w + ky) * 18 + mA + kx) * 72 + kselA) * 2);
        const uint32_t bBaseH = sB_u + (uint32_t)k * 18432 +
            (uint32_t)((oclB * 72 + koffB) * 2);
        const uint32_t bBaseR = bBaseH + 9216;

#pragma unroll
        for (int kc = 0; kc < 4; kc++) {
            uint32_t a0[4], a1[4];
            ldsm4(a0, aBase + kc * 32);
            ldsm4(a1, aBase + 2592 + kc * 32);
#pragma unroll
            for (int ng = 0; ng < 4; ng++) {
                uint32_t bh[4], br[4];
                ldsm4(bh, bBaseH + ng * 2304 + kc * 32);
                ldsm4(br, bBaseR + ng * 2304 + kc * 32);
                mma_f16(aH0[2 * ng + 0], a0, bh[0], bh[1]);
                mma_f16(aH0[2 * ng + 1], a0, bh[2], bh[3]);
                mma_f16(aH1[2 * ng + 0], a1, bh[0], bh[1]);
                mma_f16(aH1[2 * ng + 1], a1, bh[2], bh[3]);
                mma_f16(aR0[2 * ng + 0], a0, br[0], br[1]);
                mma_f16(aR0[2 * ng + 1], a0, br[2], br[3]);
                mma_f16(aR1[2 * ng + 0], a1, br[0], br[1]);
                mma_f16(aR1[2 * ng + 1], a1, br[2], br[3]);
            }
        }
    }
    __syncthreads();   // all weight/halo reads done; safe to alias s_mid

    // ---- epilogue head 1 (heatmap, 3ch) ----
#pragma unroll
    for (int rr = 0; rr < 2; rr++)
#pragma unroll
        for (int side = 0; side < 2; side++) {
            int p = (2 * w + rr) * 16 + (lane >> 2) + side * 8;
            int oc0 = (lane & 3) * 2;
#pragma unroll
            for (int nt = 0; nt < 8; nt++) {
                int oc = nt * 8 + oc0;
                float v0 = (rr == 0) ? aH0[nt][side * 2 + 0] : aH1[nt][side * 2 + 0];
                float v1 = (rr == 0) ? aH0[nt][side * 2 + 1] : aH1[nt][side * 2 + 1];
                s_mid[p * 65 + oc] = fmaxf(v0 * s_sc1[oc] + s_sh1[oc], 0.f);
                s_mid[p * 65 + oc + 1] = fmaxf(v1 * s_sc1[oc + 1] + s_sh1[oc + 1], 0.f);
            }
        }
    __syncthreads();
    {
        int p = tid;
        int yy = by + (p >> 4), xx = bx + (p & 15);
        if (yy < HH && xx < WW) {
            const float* row = s_mid + p * 65;
            float o0 = s_b2h[0], o1 = s_b2h[1], o2 = s_b2h[2];
#pragma unroll 8
            for (int c = 0; c < 64; c++) {
                float a = row[c];
                o0 += a * s_w2h[c];
                o1 += a * s_w2h[64 + c];
                o2 += a * s_w2h[128 + c];
            }
            size_t base = ((size_t)b * 3 * HH + yy) * WW + xx;
            out[base] = o0;
            out[base + (size_t)HW] = o1;
            out[base + (size_t)2 * HW] = o2;
        }
    }
    __syncthreads();

    // ---- epilogue head 2 (box_reg, 8ch) ----
#pragma unroll
    for (int rr = 0; rr < 2; rr++)
#pragma unroll
        for (int side = 0; side < 2; side++) {
            int p = (2 * w + rr) * 16 + (lane >> 2) + side * 8;
            int oc0 = (lane & 3) * 2;
#pragma unroll
            for (int nt = 0; nt < 8; nt++) {
                int oc = nt * 8 + oc0;
                float v0 = (rr == 0) ? aR0[nt][side * 2 + 0] : aR1[nt][side * 2 + 0];
                float v1 = (rr == 0) ? aR0[nt][side * 2 + 1] : aR1[nt][side * 2 + 1];
                s_mid[p * 65 + oc] = fmaxf(v0 * s_sc2[oc] + s_sh2[oc], 0.f);
                s_mid[p * 65 + oc + 1] = fmaxf(v1 * s_sc2[oc + 1] + s_sh2[oc + 1], 0.f);
            }
        }
    __syncthreads();
    {
        int p = tid;
        int yy = by + (p >> 4), xx = bx + (p & 15);
        if (yy < HH && xx < WW) {
            const float* row = s_mid + p * 65;
            float o[8];
#pragma unroll
            for (int n = 0; n < 8; n++) o[n] = s_b2r[n];
#pragma unroll 8
            for (int c = 0; c < 64; c++) {
                float a = row[c];
#pragma unroll
                for (int n = 0; n < 8; n++) o[n] += a * s_w2r[n * 64 + c];
            }
            float* rg = out + (size_t)BB * 3 * HW;
#pragma unroll
            for (int n = 0; n < 8; n++)
                rg[((size_t)(b * 8 + n) * HH + yy) * WW + xx] = o[n];
        }
    }
}

// ===========================================================================
extern "C" void kernel_launch(void* const* d_in, const int* in_sizes, int n_in,
                              void* d_out, int out_size)
{
    const float* bev   = (const float*)d_in[0];
    const float* w_sh  = (const float*)d_in[1];
    const float* g_sh  = (const float*)d_in[2];
    const float* b_sh  = (const float*)d_in[3];
    const float* m_sh  = (const float*)d_in[4];
    const float* v_sh  = (const float*)d_in[5];
    const float* w_hm1 = (const float*)d_in[6];
    const float* g_hm1 = (const float*)d_in[7];
    const float* b_hm1 = (const float*)d_in[8];
    const float* m_hm1 = (const float*)d_in[9];
    const float* v_hm1 = (const float*)d_in[10];
    const float* w_hm2 = (const float*)d_in[11];
    const float* b_hm2 = (const float*)d_in[12];
    const float* w_rg1 = (const float*)d_in[13];
    const float* g_rg1 = (const float*)d_in[14];
    const float* b_rg1 = (const float*)d_in[15];
    const float* m_rg1 = (const float*)d_in[16];
    const float* v_rg1 = (const float*)d_in[17];
    const float* w_rg2 = (const float*)d_in[18];
    const float* b_rg2 = (const float*)d_in[19];

    __half *bevh, *trh, *wi_sh, *wi_hm, *wi_rg;
    cudaGetSymbolAddress((void**)&bevh, g_bev);
    cudaGetSymbolAddress((void**)&trh, g_tr);
    cudaGetSymbolAddress((void**)&wi_sh, g_wimg_sh);
    cudaGetSymbolAddress((void**)&wi_hm, g_wimg_hm);
    cudaGetSymbolAddress((void**)&wi_rg, g_wimg_rg);

    const int DSMEM_T = 55296 + 46656;    // 101952 B (occ 2)
    const int DSMEM_H = 165888 + 46656;   // 212544 B (occ 1)
    cudaFuncSetAttribute(trunk_kernel, cudaFuncAttributeMaxDynamicSharedMemorySize, DSMEM_T);
    cudaFuncSetAttribute(heads_kernel, cudaFuncAttributeMaxDynamicSharedMemorySize, DSMEM_H);

    // 1. bev NCHW fp32 -> NHWC fp16
    nhwc_kernel<<<dim3(10, 8, BB * HH), 256>>>(bev);

    // 2. weight images
    prep_w_kernel<<<(64 * 256 * 9 + 255) / 256, 256>>>(w_sh, wi_sh, 256);
    prep_w_kernel<<<(64 * 64 * 9 + 255) / 256, 256>>>(w_hm1, wi_hm, 64);
    prep_w_kernel<<<(64 * 64 * 9 + 255) / 256, 256>>>(w_rg1, wi_rg, 64);

    dim3 grid(19, 19, BB);   // 16x16 pixel tiles

    // 3. trunk conv -> NHWC fp16
    trunk_kernel<<<grid, 256, DSMEM_T>>>(bevh, wi_sh, g_sh, b_sh, m_sh, v_sh, trh);

    // 4. fused heads -> d_out
    heads_kernel<<<grid, 256, DSMEM_H>>>(
        trh, wi_hm, wi_rg,
        g_hm1, b_hm1, m_hm1, v_hm1,
        g_rg1, b_rg1, m_rg1, v_rg1,
        w_hm2, b_hm2, w_rg2, b_rg2, (float*)d_out);
}

// round 13
// speedup vs baseline: 1.8537x; 1.0106x over previous
#include <cuda_runtime.h>
#include <cuda_fp16.h>
#include <cstdint>

#define EPSBN 1e-5f
#define HH 300
#define WW 300
#define HW 90000
#define BB 4

// ===========================================================================
// PTX helpers — baseline instructions only (target is sm_103 without 'a')
// ===========================================================================
__device__ __forceinline__ uint32_t smem_u32(const void* p) {
    uint32_t a;
    asm("{ .reg .u64 t; cvta.to.shared.u64 t, %1; cvt.u32.u64 %0, t; }"
        : "=r"(a) : "l"(p));
    return a;
}
__device__ __forceinline__ void ldsm4(uint32_t* r, uint32_t addr) {
    asm volatile("ldmatrix.sync.aligned.m8n8.x4.shared.b16 {%0,%1,%2,%3}, [%4];"
                 : "=r"(r[0]), "=r"(r[1]), "=r"(r[2]), "=r"(r[3]) : "r"(addr));
}
__device__ __forceinline__ void mma_f16(float* c, const uint32_t* a,
                                        uint32_t b0, uint32_t b1) {
    asm volatile(
        "mma.sync.aligned.m16n8k16.row.col.f32.f16.f16.f32 "
        "{%0,%1,%2,%3}, {%4,%5,%6,%7}, {%8,%9}, {%0,%1,%2,%3};"
        : "+f"(c[0]), "+f"(c[1]), "+f"(c[2]), "+f"(c[3])
        : "r"(a[0]), "r"(a[1]), "r"(a[2]), "r"(a[3]), "r"(b0), "r"(b1));
}
#define CP_ASYNC16(dst, src) \
    asm volatile("cp.async.cg.shared.global [%0], [%1], 16;" :: "r"(dst), "l"(src))
#define CP_COMMIT() asm volatile("cp.async.commit_group;" ::: "memory")
#define CP_WAIT0()  asm volatile("cp.async.wait_group 0;" ::: "memory")

// ===========================================================================
// Device scratch (allocation-guard-safe)
// ===========================================================================
__device__ __half g_bev[(size_t)BB * HW * 256];
__device__ __half g_tr[(size_t)BB * HW * 64];
__device__ __half g_wimg_sh[36 * 4608];  // trunk: 4 cch x 9 shifts, [64 oc][72]
__device__ __half g_wimg_hm[9 * 4608];
__device__ __half g_wimg_rg[9 * 4608];

// ===========================================================================
// NCHW fp32 -> NHWC fp16 (bev)
// ===========================================================================
__global__ __launch_bounds__(256) void nhwc_kernel(const float* __restrict__ in)
{
    __shared__ float tile[32][33];
    const int tx = threadIdx.x & 31, ty = threadIdx.x >> 5;
    const int w0 = blockIdx.x * 32, c0 = blockIdx.y * 32;
    const int b = blockIdx.z / HH, h = blockIdx.z % HH;
#pragma unroll
    for (int q = 0; q < 4; q++) {
        int c = c0 + ty * 4 + q, w = w0 + tx;
        tile[ty * 4 + q][tx] = (w < WW) ? in[(((size_t)b * 256 + c) * HH + h) * WW + w] : 0.f;
    }
    __syncthreads();
#pragma unroll
    for (int q = 0; q < 4; q++) {
        int w = w0 + ty * 4 + q;
        if (w >= WW) continue;
        size_t o = ((size_t)b * HW + (size_t)h * WW + w) * 256 + c0 + tx;
        g_bev[o] = __float2half_rn(tile[tx][ty * 4 + q]);
    }
}

// ===========================================================================
// Weight prep: w[oc][ci][3][3] fp32 -> per (cchunk, shift) [64 oc][72] fp16
// ===========================================================================
__global__ void prep_w_kernel(const float* __restrict__ w,
                              __half* __restrict__ dst, int CIN)
{
    int i = blockIdx.x * 256 + threadIdx.x;
    if (i >= 64 * CIN * 9) return;
    int kk = i % 9;
    int ci = (i / 9) % CIN;
    int oc = i / (9 * CIN);
    int cc = ci >> 6, c = ci & 63;
    size_t base = (size_t)(cc * 9 + kk) * 4608;
    dst[base + oc * 72 + c] = __float2half_rn(w[i]);
}

// ===========================================================================
// Trunk: conv3x3 (256->64) + BN + ReLU, single-pass fp16 mma, M=32/warp.
// CTA 256 thr (8 warps), tile 16x16 px x 64 oc; warp w = rows 2w, 2w+1.
// Rounds of 3 shifts, double-buffered B; 16 syncs total. (r12 proven config)
// ===========================================================================
__global__ __launch_bounds__(256, 2) void trunk_kernel(
    const __half* __restrict__ act, const __half* __restrict__ wimg,
    const float* __restrict__ gg, const float* __restrict__ bbp,
    const float* __restrict__ mm, const float* __restrict__ vv,
    __half* __restrict__ outp)
{
    extern __shared__ __align__(16) unsigned char dynsmem[];
    __half* sB = (__half*)dynsmem;                // 2 bufs x 27648 B = 55296
    __half* s_h = (__half*)(dynsmem + 55296);     // 324 px x 72 (46656 B)

    __shared__ float s_scale[64], s_shift[64];

    const int tid = threadIdx.x;
    const int w = tid >> 5, lane = tid & 31;
    const int bx = blockIdx.x * 16, by = blockIdx.y * 16;
    const int b = blockIdx.z;

    if (tid < 64) {
        float sc = gg[tid] * rsqrtf(vv[tid] + EPSBN);
        s_scale[tid] = sc;
        s_shift[tid] = bbp[tid] - mm[tid] * sc;
    }

    const int mA = lane & 15;
    const int kselA = (lane >> 4) * 8;
    const int oclB = (lane & 7) + ((lane >> 4) & 1) * 8;
    const int koffB = (lane & 8) ? 8 : 0;

    const uint32_t sB_u = smem_u32(sB);
    const uint32_t sh_u = smem_u32(s_h);

    float acc0[8][4], acc1[8][4];
#pragma unroll
    for (int i = 0; i < 8; i++)
#pragma unroll
        for (int j = 0; j < 4; j++) { acc0[i][j] = 0.f; acc1[i][j] = 0.f; }

    // prefetch round 0 (shifts 0..2, contiguous 27648 B)
    for (int i = tid; i < 1728; i += 256)
        CP_ASYNC16(sB_u + i * 16, (const char*)wimg + (size_t)i * 16);
    CP_COMMIT();

#pragma unroll 1
    for (int R = 0; R < 12; R++) {
        if (R % 3 == 0) {
            __syncthreads();   // previous halo readers done
            const int cc = R / 3;
            for (int idx = tid; idx < 324 * 8; idx += 256) {
                int pix = idx >> 3, j = idx & 7;
                int r = pix / 18, col = pix % 18;
                int gy = by - 1 + r, gx = bx - 1 + col;
                uint4 v = make_uint4(0, 0, 0, 0);
                if ((unsigned)gy < HH && (unsigned)gx < WW)
                    v = ((const uint4*)(act + ((size_t)b * HW + (size_t)gy * WW + gx) * 256 + cc * 64))[j];
                ((uint4*)(s_h + pix * 72))[j] = v;
            }
        }
        CP_WAIT0();
        __syncthreads();   // B data + halo visible; buf (R+1)&1 readers done
        if (R + 1 < 12) {
            uint32_t dst = sB_u + (uint32_t)((R + 1) & 1) * 27648;
            const char* src = (const char*)wimg + (size_t)(R + 1) * 27648;
            for (int i = tid; i < 1728; i += 256)
                CP_ASYNC16(dst + i * 16, src + (size_t)i * 16);
            CP_COMMIT();
        }

        const uint32_t bufB = sB_u + (uint32_t)(R & 1) * 27648;
#pragma unroll
        for (int q = 0; q < 3; q++) {
            const int k = (R % 3) * 3 + q;
            const int ky = k / 3, kx = k - 3 * ky;
            const uint32_t aBase = sh_u +
                (uint32_t)((((2 * w + ky) * 18 + mA + kx) * 72 + kselA) * 2);
            const uint32_t bBase = bufB + (uint32_t)q * 9216 +
                (uint32_t)((oclB * 72 + koffB) * 2);
#pragma unroll
            for (int kc = 0; kc < 4; kc++) {
                uint32_t a0[4], a1[4];
                ldsm4(a0, aBase + kc * 32);
                ldsm4(a1, aBase + 2592 + kc * 32);   // next row: +18*72*2 B
#pragma unroll
                for (int ng = 0; ng < 4; ng++) {
                    uint32_t bh[4];
                    ldsm4(bh, bBase + ng * 2304 + kc * 32);
                    mma_f16(acc0[2 * ng + 0], a0, bh[0], bh[1]);
                    mma_f16(acc0[2 * ng + 1], a0, bh[2], bh[3]);
                    mma_f16(acc1[2 * ng + 0], a1, bh[0], bh[1]);
                    mma_f16(acc1[2 * ng + 1], a1, bh[2], bh[3]);
                }
            }
        }
    }

    // BN + ReLU -> NHWC fp16 (2 rows per warp)
#pragma unroll
    for (int rr = 0; rr < 2; rr++) {
        const int y = by + 2 * w + rr;
#pragma unroll
        for (int side = 0; side < 2; side++) {
            int x = bx + (lane >> 2) + side * 8;
            if (y < HH && x < WW) {
                size_t base = ((size_t)b * HW + (size_t)y * WW + x) * 64;
#pragma unroll
                for (int nt = 0; nt < 8; nt++) {
                    int oc0 = nt * 8 + (lane & 3) * 2;
                    float v0 = (rr == 0) ? acc0[nt][side * 2 + 0] : acc1[nt][side * 2 + 0];
                    float v1 = (rr == 0) ? acc0[nt][side * 2 + 1] : acc1[nt][side * 2 + 1];
                    v0 = fmaxf(v0 * s_scale[oc0] + s_shift[oc0], 0.f);
                    v1 = fmaxf(v1 * s_scale[oc0 + 1] + s_shift[oc0 + 1], 0.f);
                    __half2 hp;
                    hp.x = __float2half_rn(v0);
                    hp.y = __float2half_rn(v1);
                    *(__half2*)(outp + base + oc0) = hp;
                }
            }
        }
    }
}

// ===========================================================================
// Fused heads, 512 threads / 16 warps: conv3x3 x2 + BN + ReLU + 1x1 x2.
// Warp w = row by+w, M=16 px, acc 64 fp32/thread -> 4 warps/SMSP at occ 1.
// All 9 shift-pairs resident; one burst, one sync, zero per-shift syncs.
// Both 1x1 epilogues run concurrently (thread halves).
// ===========================================================================
__global__ __launch_bounds__(512, 1) void heads_kernel(
    const __half* __restrict__ act,
    const __half* __restrict__ wimg_hm, const __half* __restrict__ wimg_rg,
    const float* __restrict__ g1, const float* __restrict__ b1,
    const float* __restrict__ m1, const float* __restrict__ v1,
    const float* __restrict__ g2, const float* __restrict__ b2,
    const float* __restrict__ m2, const float* __restrict__ v2,
    const float* __restrict__ w_hm2, const float* __restrict__ b_hm2,
    const float* __restrict__ w_rg2, const float* __restrict__ b_rg2,
    float* __restrict__ out)
{
    extern __shared__ __align__(16) unsigned char dynsmem[];
    __half* sB = (__half*)dynsmem;                // 9 x (hm 9216 | rg 9216) = 165888 B
    __half* s_h = (__half*)(dynsmem + 165888);    // 324 x 72 (46656 B) -> 212544 total
    float* s_midH = (float*)dynsmem;              // epilogue alias: 256*65*4 = 66560 B
    float* s_midR = (float*)(dynsmem + 66560);    // second buffer (ends 133120 < 165888)

    __shared__ float s_sc1[64], s_sh1[64], s_sc2[64], s_sh2[64];
    __shared__ float s_w2h[3 * 64], s_w2r[8 * 64];
    __shared__ float s_b2h[3], s_b2r[8];

    const int tid = threadIdx.x;
    const int w = tid >> 5, lane = tid & 31;
    const int bx = blockIdx.x * 16, by = blockIdx.y * 16;
    const int b = blockIdx.z;

    if (tid < 64) {
        float sc = g1[tid] * rsqrtf(v1[tid] + EPSBN);
        s_sc1[tid] = sc;
        s_sh1[tid] = b1[tid] - m1[tid] * sc;
        float sc2 = g2[tid] * rsqrtf(v2[tid] + EPSBN);
        s_sc2[tid] = sc2;
        s_sh2[tid] = b2[tid] - m2[tid] * sc2;
    }
    for (int i = tid; i < 192; i += 512) s_w2h[i] = w_hm2[i];
    for (int i = tid; i < 512; i += 512) s_w2r[i] = w_rg2[i];
    if (tid < 3) s_b2h[tid] = b_hm2[tid];
    if (tid < 8) s_b2r[tid] = b_rg2[tid];

    const int mA = lane & 15;
    const int kselA = (lane >> 4) * 8;
    const int oclB = (lane & 7) + ((lane >> 4) & 1) * 8;
    const int koffB = (lane & 8) ? 8 : 0;

    const uint32_t sB_u = smem_u32(sB);
    const uint32_t sh_u = smem_u32(s_h);

    float aH[8][4], aR[8][4];
#pragma unroll
    for (int i = 0; i < 8; i++)
#pragma unroll
        for (int j = 0; j < 4; j++) { aH[i][j] = 0.f; aR[i][j] = 0.f; }

    // one burst: all 9 shifts, both heads (165888 B)
    for (int i = tid; i < 5184; i += 512) {
        int sh = i / 576, j = i - sh * 576;
        uint32_t dst = sB_u + (uint32_t)sh * 18432 + (uint32_t)j * 16;
        CP_ASYNC16(dst, (const char*)wimg_hm + (size_t)i * 16);
        CP_ASYNC16(dst + 9216, (const char*)wimg_rg + (size_t)i * 16);
    }
    CP_COMMIT();

    // stage halo once (CIN = 64): 324 px, 8 uint4 per pixel
    for (int idx = tid; idx < 324 * 8; idx += 512) {
        int pix = idx >> 3, j = idx & 7;
        int r = pix / 18, col = pix % 18;
        int gy = by - 1 + r, gx = bx - 1 + col;
        uint4 v = make_uint4(0, 0, 0, 0);
        if ((unsigned)gy < HH && (unsigned)gx < WW)
            v = ((const uint4*)(act + ((size_t)b * HW + (size_t)gy * WW + gx) * 64))[j];
        ((uint4*)(s_h + pix * 72))[j] = v;
    }

    CP_WAIT0();
    __syncthreads();   // the only pre-epilogue sync

#pragma unroll 1
    for (int k = 0; k < 9; k++) {
        const int ky = k / 3, kx = k - 3 * ky;
        const uint32_t aBase = sh_u +
            (uint32_t)((((w + ky) * 18 + mA + kx) * 72 + kselA) * 2);
        const uint32_t bBaseH = sB_u + (uint32_t)k * 18432 +
            (uint32_t)((oclB * 72 + koffB) * 2);
        const uint32_t bBaseR = bBaseH + 9216;

#pragma unroll
        for (int kc = 0; kc < 4; kc++) {
            uint32_t a[4];
            ldsm4(a, aBase + kc * 32);
#pragma unroll
            for (int ng = 0; ng < 4; ng++) {
                uint32_t bh[4], br[4];
                ldsm4(bh, bBaseH + ng * 2304 + kc * 32);
                ldsm4(br, bBaseR + ng * 2304 + kc * 32);
                mma_f16(aH[2 * ng + 0], a, bh[0], bh[1]);
                mma_f16(aH[2 * ng + 1], a, bh[2], bh[3]);
                mma_f16(aR[2 * ng + 0], a, br[0], br[1]);
                mma_f16(aR[2 * ng + 1], a, br[2], br[3]);
            }
        }
    }
    __syncthreads();   // all weight/halo reads done; safe to alias s_mid

    // ---- BN + ReLU into both mid buffers ----
#pragma unroll
    for (int side = 0; side < 2; side++) {
        int p = w * 16 + (lane >> 2) + side * 8;
        int oc0 = (lane & 3) * 2;
#pragma unroll
        for (int nt = 0; nt < 8; nt++) {
            int oc = nt * 8 + oc0;
            s_midH[p * 65 + oc] = fmaxf(aH[nt][side * 2 + 0] * s_sc1[oc] + s_sh1[oc], 0.f);
            s_midH[p * 65 + oc + 1] = fmaxf(aH[nt][side * 2 + 1] * s_sc1[oc + 1] + s_sh1[oc + 1], 0.f);
            s_midR[p * 65 + oc] = fmaxf(aR[nt][side * 2 + 0] * s_sc2[oc] + s_sh2[oc], 0.f);
            s_midR[p * 65 + oc + 1] = fmaxf(aR[nt][side * 2 + 1] * s_sc2[oc + 1] + s_sh2[oc + 1], 0.f);
        }
    }
    __syncthreads();

    // ---- parallel 1x1 epilogues: lower half heatmap, upper half box_reg ----
    if (tid < 256) {
        int p = tid;
        int yy = by + (p >> 4), xx = bx + (p & 15);
        if (yy < HH && xx < WW) {
            const float* row = s_midH + p * 65;
            float o0 = s_b2h[0], o1 = s_b2h[1], o2 = s_b2h[2];
#pragma unroll 8
            for (int c = 0; c < 64; c++) {
                float a = row[c];
                o0 += a * s_w2h[c];
                o1 += a * s_w2h[64 + c];
                o2 += a * s_w2h[128 + c];
            }
            size_t base = ((size_t)b * 3 * HH + yy) * WW + xx;
            out[base] = o0;
            out[base + (size_t)HW] = o1;
            out[base + (size_t)2 * HW] = o2;
        }
    } else {
        int p = tid - 256;
        int yy = by + (p >> 4), xx = bx + (p & 15);
        if (yy < HH && xx < WW) {
            const float* row = s_midR + p * 65;
            float o[8];
#pragma unroll
            for (int n = 0; n < 8; n++) o[n] = s_b2r[n];
#pragma unroll 8
            for (int c = 0; c < 64; c++) {
                float a = row[c];
#pragma unroll
                for (int n = 0; n < 8; n++) o[n] += a * s_w2r[n * 64 + c];
            }
            float* rg = out + (size_t)BB * 3 * HW;
#pragma unroll
            for (int n = 0; n < 8; n++)
                rg[((size_t)(b * 8 + n) * HH + yy) * WW + xx] = o[n];
        }
    }
}

// ===========================================================================
extern "C" void kernel_launch(void* const* d_in, const int* in_sizes, int n_in,
                              void* d_out, int out_size)
{
    const float* bev   = (const float*)d_in[0];
    const float* w_sh  = (const float*)d_in[1];
    const float* g_sh  = (const float*)d_in[2];
    const float* b_sh  = (const float*)d_in[3];
    const float* m_sh  = (const float*)d_in[4];
    const float* v_sh  = (const float*)d_in[5];
    const float* w_hm1 = (const float*)d_in[6];
    const float* g_hm1 = (const float*)d_in[7];
    const float* b_hm1 = (const float*)d_in[8];
    const float* m_hm1 = (const float*)d_in[9];
    const float* v_hm1 = (const float*)d_in[10];
    const float* w_hm2 = (const float*)d_in[11];
    const float* b_hm2 = (const float*)d_in[12];
    const float* w_rg1 = (const float*)d_in[13];
    const float* g_rg1 = (const float*)d_in[14];
    const float* b_rg1 = (const float*)d_in[15];
    const float* m_rg1 = (const float*)d_in[16];
    const float* v_rg1 = (const float*)d_in[17];
    const float* w_rg2 = (const float*)d_in[18];
    const float* b_rg2 = (const float*)d_in[19];

    __half *bevh, *trh, *wi_sh, *wi_hm, *wi_rg;
    cudaGetSymbolAddress((void**)&bevh, g_bev);
    cudaGetSymbolAddress((void**)&trh, g_tr);
    cudaGetSymbolAddress((void**)&wi_sh, g_wimg_sh);
    cudaGetSymbolAddress((void**)&wi_hm, g_wimg_hm);
    cudaGetSymbolAddress((void**)&wi_rg, g_wimg_rg);

    const int DSMEM_T = 55296 + 46656;    // 101952 B (occ 2)
    const int DSMEM_H = 165888 + 46656;   // 212544 B (occ 1, 16 warps)
    cudaFuncSetAttribute(trunk_kernel, cudaFuncAttributeMaxDynamicSharedMemorySize, DSMEM_T);
    cudaFuncSetAttribute(heads_kernel, cudaFuncAttributeMaxDynamicSharedMemorySize, DSMEM_H);

    // 1. bev NCHW fp32 -> NHWC fp16
    nhwc_kernel<<<dim3(10, 8, BB * HH), 256>>>(bev);

    // 2. weight images
    prep_w_kernel<<<(64 * 256 * 9 + 255) / 256, 256>>>(w_sh, wi_sh, 256);
    prep_w_kernel<<<(64 * 64 * 9 + 255) / 256, 256>>>(w_hm1, wi_hm, 64);
    prep_w_kernel<<<(64 * 64 * 9 + 255) / 256, 256>>>(w_rg1, wi_rg, 64);

    dim3 grid(19, 19, BB);   // 16x16 pixel tiles

    // 3. trunk conv -> NHWC fp16
    trunk_kernel<<<grid, 256, DSMEM_T>>>(bevh, wi_sh, g_sh, b_sh, m_sh, v_sh, trh);

    // 4. fused heads (512 threads) -> d_out
    heads_kernel<<<grid, 512, DSMEM_H>>>(
        trh, wi_hm, wi_rg,
        g_hm1, b_hm1, m_hm1, v_hm1,
        g_rg1, b_rg1, m_rg1, v_rg1,
        w_hm2, b_hm2, w_rg2, b_rg2, (float*)d_out);
}

// round 14
// speedup vs baseline: 1.9766x; 1.0663x over previous
#include <cuda_runtime.h>
#include <cuda_fp16.h>
#include <cstdint>

#define EPSBN 1e-5f
#define HH 300
#define WW 300
#define HW 90000
#define BB 4

// ===========================================================================
// PTX helpers — baseline instructions only (target is sm_103 without 'a')
// ===========================================================================
__device__ __forceinline__ uint32_t smem_u32(const void* p) {
    uint32_t a;
    asm("{ .reg .u64 t; cvta.to.shared.u64 t, %1; cvt.u32.u64 %0, t; }"
        : "=r"(a) : "l"(p));
    return a;
}
__device__ __forceinline__ void ldsm4(uint32_t* r, uint32_t addr) {
    asm volatile("ldmatrix.sync.aligned.m8n8.x4.shared.b16 {%0,%1,%2,%3}, [%4];"
                 : "=r"(r[0]), "=r"(r[1]), "=r"(r[2]), "=r"(r[3]) : "r"(addr));
}
__device__ __forceinline__ void mma_f16(float* c, const uint32_t* a,
                                        uint32_t b0, uint32_t b1) {
    asm volatile(
        "mma.sync.aligned.m16n8k16.row.col.f32.f16.f16.f32 "
        "{%0,%1,%2,%3}, {%4,%5,%6,%7}, {%8,%9}, {%0,%1,%2,%3};"
        : "+f"(c[0]), "+f"(c[1]), "+f"(c[2]), "+f"(c[3])
        : "r"(a[0]), "r"(a[1]), "r"(a[2]), "r"(a[3]), "r"(b0), "r"(b1));
}
#define CP_ASYNC16(dst, src) \
    asm volatile("cp.async.cg.shared.global [%0], [%1], 16;" :: "r"(dst), "l"(src))
#define CP_ASYNC16Z(dst, src, sz) \
    asm volatile("cp.async.cg.shared.global [%0], [%1], 16, %2;" \
                 :: "r"(dst), "l"(src), "r"(sz))
#define CP_COMMIT() asm volatile("cp.async.commit_group;" ::: "memory")
#define CP_WAIT0()  asm volatile("cp.async.wait_group 0;" ::: "memory")

// ===========================================================================
// Device scratch (allocation-guard-safe)
// ===========================================================================
__device__ __half g_bev[(size_t)BB * HW * 256];
__device__ __half g_tr[(size_t)BB * HW * 64];
__device__ __half g_wimg_sh[36 * 4608];  // trunk: 4 cch x 9 shifts, [64 oc][72]
__device__ __half g_wimg_hm[9 * 4608];
__device__ __half g_wimg_rg[9 * 4608];

// ===========================================================================
// NCHW fp32 -> NHWC fp16 (bev)
// ===========================================================================
__global__ __launch_bounds__(256) void nhwc_kernel(const float* __restrict__ in)
{
    __shared__ float tile[32][33];
    const int tx = threadIdx.x & 31, ty = threadIdx.x >> 5;
    const int w0 = blockIdx.x * 32, c0 = blockIdx.y * 32;
    const int b = blockIdx.z / HH, h = blockIdx.z % HH;
#pragma unroll
    for (int q = 0; q < 4; q++) {
        int c = c0 + ty * 4 + q, w = w0 + tx;
        tile[ty * 4 + q][tx] = (w < WW) ? in[(((size_t)b * 256 + c) * HH + h) * WW + w] : 0.f;
    }
    __syncthreads();
#pragma unroll
    for (int q = 0; q < 4; q++) {
        int w = w0 + ty * 4 + q;
        if (w >= WW) continue;
        size_t o = ((size_t)b * HW + (size_t)h * WW + w) * 256 + c0 + tx;
        g_bev[o] = __float2half_rn(tile[tx][ty * 4 + q]);
    }
}

// ===========================================================================
// Weight prep: w[oc][ci][3][3] fp32 -> per (cchunk, shift) [64 oc][72] fp16
// ===========================================================================
__global__ void prep_w_kernel(const float* __restrict__ w,
                              __half* __restrict__ dst, int CIN)
{
    int i = blockIdx.x * 256 + threadIdx.x;
    if (i >= 64 * CIN * 9) return;
    int kk = i % 9;
    int ci = (i / 9) % CIN;
    int oc = i / (9 * CIN);
    int cc = ci >> 6, c = ci & 63;
    size_t base = (size_t)(cc * 9 + kk) * 4608;
    dst[base + oc * 72 + c] = __float2half_rn(w[i]);
}

// ===========================================================================
// Trunk: conv3x3 (256->64) + BN + ReLU, single-pass fp16 mma, M=32/warp.
// CTA 256 thr (8 warps), tile 16x16 px x 64 oc; warp w = rows 2w, 2w+1.
// Rounds of 3 shifts, double-buffered B; halo staged via cp.async zero-fill.
// ===========================================================================
__global__ __launch_bounds__(256, 2) void trunk_kernel(
    const __half* __restrict__ act, const __half* __restrict__ wimg,
    const float* __restrict__ gg, const float* __restrict__ bbp,
    const float* __restrict__ mm, const float* __restrict__ vv,
    __half* __restrict__ outp)
{
    extern __shared__ __align__(16) unsigned char dynsmem[];
    __half* sB = (__half*)dynsmem;                // 2 bufs x 27648 B = 55296
    __half* s_h = (__half*)(dynsmem + 55296);     // 324 px x 72 (46656 B)

    __shared__ float s_scale[64], s_shift[64];

    const int tid = threadIdx.x;
    const int w = tid >> 5, lane = tid & 31;
    const int bx = blockIdx.x * 16, by = blockIdx.y * 16;
    const int b = blockIdx.z;

    if (tid < 64) {
        float sc = gg[tid] * rsqrtf(vv[tid] + EPSBN);
        s_scale[tid] = sc;
        s_shift[tid] = bbp[tid] - mm[tid] * sc;
    }

    const int mA = lane & 15;
    const int kselA = (lane >> 4) * 8;
    const int oclB = (lane & 7) + ((lane >> 4) & 1) * 8;
    const int koffB = (lane & 8) ? 8 : 0;

    const uint32_t sB_u = smem_u32(sB);
    const uint32_t sh_u = smem_u32(s_h);

    float acc0[8][4], acc1[8][4];
#pragma unroll
    for (int i = 0; i < 8; i++)
#pragma unroll
        for (int j = 0; j < 4; j++) { acc0[i][j] = 0.f; acc1[i][j] = 0.f; }

    // prefetch round 0 (shifts 0..2, contiguous 27648 B)
    for (int i = tid; i < 1728; i += 256)
        CP_ASYNC16(sB_u + i * 16, (const char*)wimg + (size_t)i * 16);
    CP_COMMIT();

#pragma unroll 1
    for (int R = 0; R < 12; R++) {
        if (R % 3 == 0) {
            __syncthreads();   // previous halo readers done
            // stage halo via cp.async (zero-fill OOB): 324 px x 64 ch
            const int cc = R / 3;
            for (int idx = tid; idx < 324 * 8; idx += 256) {
                int pix = idx >> 3, j = idx & 7;
                int r = pix / 18, col = pix % 18;
                int gy = by - 1 + r, gx = bx - 1 + col;
                bool ok = ((unsigned)gy < HH) && ((unsigned)gx < WW);
                const char* src = (const char*)(act +
                    (ok ? ((size_t)b * HW + (size_t)gy * WW + gx) * 256 + cc * 64 + j * 8
                        : (size_t)0));
                CP_ASYNC16Z(sh_u + (uint32_t)(pix * 144 + j * 16), src, ok ? 16 : 0);
            }
            CP_COMMIT();
        }
        CP_WAIT0();
        __syncthreads();   // B data + halo visible; buf (R+1)&1 readers done
        if (R + 1 < 12) {
            uint32_t dst = sB_u + (uint32_t)((R + 1) & 1) * 27648;
            const char* src = (const char*)wimg + (size_t)(R + 1) * 27648;
            for (int i = tid; i < 1728; i += 256)
                CP_ASYNC16(dst + i * 16, src + (size_t)i * 16);
            CP_COMMIT();
        }

        const uint32_t bufB = sB_u + (uint32_t)(R & 1) * 27648;
#pragma unroll
        for (int q = 0; q < 3; q++) {
            const int k = (R % 3) * 3 + q;
            const int ky = k / 3, kx = k - 3 * ky;
            const uint32_t aBase = sh_u +
                (uint32_t)((((2 * w + ky) * 18 + mA + kx) * 72 + kselA) * 2);
            const uint32_t bBase = bufB + (uint32_t)q * 9216 +
                (uint32_t)((oclB * 72 + koffB) * 2);
#pragma unroll
            for (int kc = 0; kc < 4; kc++) {
                uint32_t a0[4], a1[4];
                ldsm4(a0, aBase + kc * 32);
                ldsm4(a1, aBase + 2592 + kc * 32);   // next row: +18*72*2 B
#pragma unroll
                for (int ng = 0; ng < 4; ng++) {
                    uint32_t bh[4];
                    ldsm4(bh, bBase + ng * 2304 + kc * 32);
                    mma_f16(acc0[2 * ng + 0], a0, bh[0], bh[1]);
                    mma_f16(acc0[2 * ng + 1], a0, bh[2], bh[3]);
                    mma_f16(acc1[2 * ng + 0], a1, bh[0], bh[1]);
                    mma_f16(acc1[2 * ng + 1], a1, bh[2], bh[3]);
                }
            }
        }
    }

    // BN + ReLU -> NHWC fp16 (2 rows per warp)
#pragma unroll
    for (int rr = 0; rr < 2; rr++) {
        const int y = by + 2 * w + rr;
#pragma unroll
        for (int side = 0; side < 2; side++) {
            int x = bx + (lane >> 2) + side * 8;
            if (y < HH && x < WW) {
                size_t base = ((size_t)b * HW + (size_t)y * WW + x) * 64;
#pragma unroll
                for (int nt = 0; nt < 8; nt++) {
                    int oc0 = nt * 8 + (lane & 3) * 2;
                    float v0 = (rr == 0) ? acc0[nt][side * 2 + 0] : acc1[nt][side * 2 + 0];
                    float v1 = (rr == 0) ? acc0[nt][side * 2 + 1] : acc1[nt][side * 2 + 1];
                    v0 = fmaxf(v0 * s_scale[oc0] + s_shift[oc0], 0.f);
                    v1 = fmaxf(v1 * s_scale[oc0 + 1] + s_shift[oc0 + 1], 0.f);
                    __half2 hp;
                    hp.x = __float2half_rn(v0);
                    hp.y = __float2half_rn(v1);
                    *(__half2*)(outp + base + oc0) = hp;
                }
            }
        }
    }
}

// ===========================================================================
// Fused heads, 512 thr / 16 warps = 8 row-pairs x 2 heads.
// Warp (i, j): rows 2i,2i+1 of head j (j=0 heatmap, j=1 box_reg).
// F=2 rows x G=4 oc-groups -> 24 ldsm / 64 mma per shift, acc 64 regs.
// All 9 shift-pairs resident; one burst, one sync, zero per-shift syncs.
// ===========================================================================
__global__ __launch_bounds__(512, 1) void heads_kernel(
    const __half* __restrict__ act,
    const __half* __restrict__ wimg_hm, const __half* __restrict__ wimg_rg,
    const float* __restrict__ g1, const float* __restrict__ b1,
    const float* __restrict__ m1, const float* __restrict__ v1,
    const float* __restrict__ g2, const float* __restrict__ b2,
    const float* __restrict__ m2, const float* __restrict__ v2,
    const float* __restrict__ w_hm2, const float* __restrict__ b_hm2,
    const float* __restrict__ w_rg2, const float* __restrict__ b_rg2,
    float* __restrict__ out)
{
    extern __shared__ __align__(16) unsigned char dynsmem[];
    __half* sB = (__half*)dynsmem;                // 9 x (hm 9216 | rg 9216) = 165888 B
    __half* s_h = (__half*)(dynsmem + 165888);    // 324 x 72 (46656 B) -> 212544 total
    float* s_midH = (float*)dynsmem;              // epilogue alias: 256*65*4 = 66560 B
    float* s_midR = (float*)(dynsmem + 66560);    // second buffer (ends 133120 < 165888)

    __shared__ float s_sc1[64], s_sh1[64], s_sc2[64], s_sh2[64];
    __shared__ float s_w2h[3 * 64], s_w2r[8 * 64];
    __shared__ float s_b2h[3], s_b2r[8];

    const int tid = threadIdx.x;
    const int w = tid >> 5, lane = tid & 31;
    const int wi = w & 7;           // row-pair index
    const int wj = w >> 3;          // head index: 0=hm, 1=rg
    const int bx = blockIdx.x * 16, by = blockIdx.y * 16;
    const int b = blockIdx.z;

    if (tid < 64) {
        float sc = g1[tid] * rsqrtf(v1[tid] + EPSBN);
        s_sc1[tid] = sc;
        s_sh1[tid] = b1[tid] - m1[tid] * sc;
        float sc2 = g2[tid] * rsqrtf(v2[tid] + EPSBN);
        s_sc2[tid] = sc2;
        s_sh2[tid] = b2[tid] - m2[tid] * sc2;
    }
    for (int i = tid; i < 192; i += 512) s_w2h[i] = w_hm2[i];
    for (int i = tid; i < 512; i += 512) s_w2r[i] = w_rg2[i];
    if (tid < 3) s_b2h[tid] = b_hm2[tid];
    if (tid < 8) s_b2r[tid] = b_rg2[tid];

    const int mA = lane & 15;
    const int kselA = (lane >> 4) * 8;
    const int oclB = (lane & 7) + ((lane >> 4) & 1) * 8;
    const int koffB = (lane & 8) ? 8 : 0;

    const uint32_t sB_u = smem_u32(sB);
    const uint32_t sh_u = smem_u32(s_h);

    float acc0[8][4], acc1[8][4];   // rows 2wi, 2wi+1 of head wj
#pragma unroll
    for (int i = 0; i < 8; i++)
#pragma unroll
        for (int j = 0; j < 4; j++) { acc0[i][j] = 0.f; acc1[i][j] = 0.f; }

    // one burst: all 9 shifts, both heads (165888 B)
    for (int i = tid; i < 5184; i += 512) {
        int sh = i / 576, j = i - sh * 576;
        uint32_t dst = sB_u + (uint32_t)sh * 18432 + (uint32_t)j * 16;
        CP_ASYNC16(dst, (const char*)wimg_hm + (size_t)i * 16);
        CP_ASYNC16(dst + 9216, (const char*)wimg_rg + (size_t)i * 16);
    }
    CP_COMMIT();

    // stage halo once (CIN = 64): 324 px, 8 uint4 per pixel
    for (int idx = tid; idx < 324 * 8; idx += 512) {
        int pix = idx >> 3, j = idx & 7;
        int r = pix / 18, col = pix % 18;
        int gy = by - 1 + r, gx = bx - 1 + col;
        uint4 v = make_uint4(0, 0, 0, 0);
        if ((unsigned)gy < HH && (unsigned)gx < WW)
            v = ((const uint4*)(act + ((size_t)b * HW + (size_t)gy * WW + gx) * 64))[j];
        ((uint4*)(s_h + pix * 72))[j] = v;
    }

    CP_WAIT0();
    __syncthreads();   // the only pre-epilogue sync

    const uint32_t headOff = (uint32_t)wj * 9216;

#pragma unroll 1
    for (int k = 0; k < 9; k++) {
        const int ky = k / 3, kx = k - 3 * ky;
        const uint32_t aBase = sh_u +
            (uint32_t)((((2 * wi + ky) * 18 + mA + kx) * 72 + kselA) * 2);
        const uint32_t bBase = sB_u + (uint32_t)k * 18432 + headOff +
            (uint32_t)((oclB * 72 + koffB) * 2);

#pragma unroll
        for (int kc = 0; kc < 4; kc++) {
            uint32_t a0[4], a1[4];
            ldsm4(a0, aBase + kc * 32);
            ldsm4(a1, aBase + 2592 + kc * 32);
#pragma unroll
            for (int ng = 0; ng < 4; ng++) {
                uint32_t bh[4];
                ldsm4(bh, bBase + ng * 2304 + kc * 32);
                mma_f16(acc0[2 * ng + 0], a0, bh[0], bh[1]);
                mma_f16(acc0[2 * ng + 1], a0, bh[2], bh[3]);
                mma_f16(acc1[2 * ng + 0], a1, bh[0], bh[1]);
                mma_f16(acc1[2 * ng + 1], a1, bh[2], bh[3]);
            }
        }
    }
    __syncthreads();   // all weight/halo reads done; safe to alias s_mid

    // ---- BN + ReLU into this head's mid buffer (rows 2wi, 2wi+1) ----
    {
        const float* sc = wj ? s_sc2 : s_sc1;
        const float* sh = wj ? s_sh2 : s_sh1;
        float* mid = wj ? s_midR : s_midH;
#pragma unroll
        for (int rr = 0; rr < 2; rr++)
#pragma unroll
            for (int side = 0; side < 2; side++) {
                int p = (2 * wi + rr) * 16 + (lane >> 2) + side * 8;
                int oc0 = (lane & 3) * 2;
#pragma unroll
                for (int nt = 0; nt < 8; nt++) {
                    int oc = nt * 8 + oc0;
                    float v0 = (rr == 0) ? acc0[nt][side * 2 + 0] : acc1[nt][side * 2 + 0];
                    float v1 = (rr == 0) ? acc0[nt][side * 2 + 1] : acc1[nt][side * 2 + 1];
                    mid[p * 65 + oc] = fmaxf(v0 * sc[oc] + sh[oc], 0.f);
                    mid[p * 65 + oc + 1] = fmaxf(v1 * sc[oc + 1] + sh[oc + 1], 0.f);
                }
            }
    }
    __syncthreads();

    // ---- parallel 1x1 epilogues: lower half heatmap, upper half box_reg ----
    if (tid < 256) {
        int p = tid;
        int yy = by + (p >> 4), xx = bx + (p & 15);
        if (yy < HH && xx < WW) {
            const float* row = s_midH + p * 65;
            float o0 = s_b2h[0], o1 = s_b2h[1], o2 = s_b2h[2];
#pragma unroll 8
            for (int c = 0; c < 64; c++) {
                float a = row[c];
                o0 += a * s_w2h[c];
                o1 += a * s_w2h[64 + c];
                o2 += a * s_w2h[128 + c];
            }
            size_t base = ((size_t)b * 3 * HH + yy) * WW + xx;
            out[base] = o0;
            out[base + (size_t)HW] = o1;
            out[base + (size_t)2 * HW] = o2;
        }
    } else {
        int p = tid - 256;
        int yy = by + (p >> 4), xx = bx + (p & 15);
        if (yy < HH && xx < WW) {
            const float* row = s_midR + p * 65;
            float o[8];
#pragma unroll
            for (int n = 0; n < 8; n++) o[n] = s_b2r[n];
#pragma unroll 8
            for (int c = 0; c < 64; c++) {
                float a = row[c];
#pragma unroll
                for (int n = 0; n < 8; n++) o[n] += a * s_w2r[n * 64 + c];
            }
            float* rg = out + (size_t)BB * 3 * HW;
#pragma unroll
            for (int n = 0; n < 8; n++)
                rg[((size_t)(b * 8 + n) * HH + yy) * WW + xx] = o[n];
        }
    }
}

// ===========================================================================
extern "C" void kernel_launch(void* const* d_in, const int* in_sizes, int n_in,
                              void* d_out, int out_size)
{
    const float* bev   = (const float*)d_in[0];
    const float* w_sh  = (const float*)d_in[1];
    const float* g_sh  = (const float*)d_in[2];
    const float* b_sh  = (const float*)d_in[3];
    const float* m_sh  = (const float*)d_in[4];
    const float* v_sh  = (const float*)d_in[5];
    const float* w_hm1 = (const float*)d_in[6];
    const float* g_hm1 = (const float*)d_in[7];
    const float* b_hm1 = (const float*)d_in[8];
    const float* m_hm1 = (const float*)d_in[9];
    const float* v_hm1 = (const float*)d_in[10];
    const float* w_hm2 = (const float*)d_in[11];
    const float* b_hm2 = (const float*)d_in[12];
    const float* w_rg1 = (const float*)d_in[13];
    const float* g_rg1 = (const float*)d_in[14];
    const float* b_rg1 = (const float*)d_in[15];
    const float* m_rg1 = (const float*)d_in[16];
    const float* v_rg1 = (const float*)d_in[17];
    const float* w_rg2 = (const float*)d_in[18];
    const float* b_rg2 = (const float*)d_in[19];

    __half *bevh, *trh, *wi_sh, *wi_hm, *wi_rg;
    cudaGetSymbolAddress((void**)&bevh, g_bev);
    cudaGetSymbolAddress((void**)&trh, g_tr);
    cudaGetSymbolAddress((void**)&wi_sh, g_wimg_sh);
    cudaGetSymbolAddress((void**)&wi_hm, g_wimg_hm);
    cudaGetSymbolAddress((void**)&wi_rg, g_wimg_rg);

    const int DSMEM_T = 55296 + 46656;    // 101952 B (occ 2)
    const int DSMEM_H = 165888 + 46656;   // 212544 B (occ 1, 16 warps)
    cudaFuncSetAttribute(trunk_kernel, cudaFuncAttributeMaxDynamicSharedMemorySize, DSMEM_T);
    cudaFuncSetAttribute(heads_kernel, cudaFuncAttributeMaxDynamicSharedMemorySize, DSMEM_H);

    // 1. bev NCHW fp32 -> NHWC fp16
    nhwc_kernel<<<dim3(10, 8, BB * HH), 256>>>(bev);

    // 2. weight images
    prep_w_kernel<<<(64 * 256 * 9 + 255) / 256, 256>>>(w_sh, wi_sh, 256);
    prep_w_kernel<<<(64 * 64 * 9 + 255) / 256, 256>>>(w_hm1, wi_hm, 64);
    prep_w_kernel<<<(64 * 64 * 9 + 255) / 256, 256>>>(w_rg1, wi_rg, 64);

    dim3 grid(19, 19, BB);   // 16x16 pixel tiles

    // 3. trunk conv -> NHWC fp16
    trunk_kernel<<<grid, 256, DSMEM_T>>>(bevh, wi_sh, g_sh, b_sh, m_sh, v_sh, trh);

    // 4. fused heads (512 threads, warp = row-pair x head) -> d_out
    heads_kernel<<<grid, 512, DSMEM_H>>>(
        trh, wi_hm, wi_rg,
        g_hm1, b_hm1, m_hm1, v_hm1,
        g_rg1, b_rg1, m_rg1, v_rg1,
        w_hm2, b_hm2, w_rg2, b_rg2, (float*)d_out);
}

// round 15
// speedup vs baseline: 1.9805x; 1.0020x over previous
#include <cuda_runtime.h>
#include <cuda_fp16.h>
#include <cstdint>

#define EPSBN 1e-5f
#define HH 300
#define WW 300
#define HW 90000
#define BB 4

// ===========================================================================
// PTX helpers — baseline instructions only (target is sm_103 without 'a')
// ===========================================================================
__device__ __forceinline__ uint32_t smem_u32(const void* p) {
    uint32_t a;
    asm("{ .reg .u64 t; cvta.to.shared.u64 t, %1; cvt.u32.u64 %0, t; }"
        : "=r"(a) : "l"(p));
    return a;
}
__device__ __forceinline__ void ldsm4(uint32_t* r, uint32_t addr) {
    asm volatile("ldmatrix.sync.aligned.m8n8.x4.shared.b16 {%0,%1,%2,%3}, [%4];"
                 : "=r"(r[0]), "=r"(r[1]), "=r"(r[2]), "=r"(r[3]) : "r"(addr));
}
__device__ __forceinline__ void mma_f16(float* c, const uint32_t* a,
                                        uint32_t b0, uint32_t b1) {
    asm volatile(
        "mma.sync.aligned.m16n8k16.row.col.f32.f16.f16.f32 "
        "{%0,%1,%2,%3}, {%4,%5,%6,%7}, {%8,%9}, {%0,%1,%2,%3};"
        : "+f"(c[0]), "+f"(c[1]), "+f"(c[2]), "+f"(c[3])
        : "r"(a[0]), "r"(a[1]), "r"(a[2]), "r"(a[3]), "r"(b0), "r"(b1));
}
#define CP_ASYNC16(dst, src) \
    asm volatile("cp.async.cg.shared.global [%0], [%1], 16;" :: "r"(dst), "l"(src))
#define CP_ASYNC16Z(dst, src, sz) \
    asm volatile("cp.async.cg.shared.global [%0], [%1], 16, %2;" \
                 :: "r"(dst), "l"(src), "r"(sz))
#define CP_COMMIT() asm volatile("cp.async.commit_group;" ::: "memory")
#define CP_WAIT0()  asm volatile("cp.async.wait_group 0;" ::: "memory")
#define CP_WAIT1()  asm volatile("cp.async.wait_group 1;" ::: "memory")
#define CP_WAIT2()  asm volatile("cp.async.wait_group 2;" ::: "memory")

// ===========================================================================
// Device scratch (allocation-guard-safe)
// ===========================================================================
__device__ __half g_bev[(size_t)BB * HW * 256];
__device__ __half g_tr[(size_t)BB * HW * 64];
__device__ __half g_wimg_sh[36 * 4608];  // trunk: 4 cch x 9 shifts, [64 oc][72]
__device__ __half g_wimg_hm[9 * 4608];
__device__ __half g_wimg_rg[9 * 4608];

// ===========================================================================
// Merged prologue: NCHW fp32 -> NHWC fp16 (z < 1200) PLUS all weight-image
// prep (z == 1200 slice, 80 CTAs) in one launch — preps run concurrently
// with the bev conversion instead of serializing after it.
// ===========================================================================
__device__ __forceinline__ void prep_one(const float* __restrict__ w,
                                         __half* __restrict__ dst,
                                         int CIN, int i) {
    int kk = i % 9;
    int ci = (i / 9) % CIN;
    int oc = i / (9 * CIN);
    int cc = ci >> 6, c = ci & 63;
    dst[(size_t)(cc * 9 + kk) * 4608 + oc * 72 + c] = __float2half_rn(w[i]);
}

__global__ __launch_bounds__(256) void prologue_kernel(
    const float* __restrict__ in,
    const float* __restrict__ w_sh,
    const float* __restrict__ w_hm,
    const float* __restrict__ w_rg)
{
    __shared__ float tile[32][33];
    if (blockIdx.z < 1200) {
        const int tx = threadIdx.x & 31, ty = threadIdx.x >> 5;
        const int w0 = blockIdx.x * 32, c0 = blockIdx.y * 32;
        const int b = blockIdx.z / HH, h = blockIdx.z % HH;
#pragma unroll
        for (int q = 0; q < 4; q++) {
            int c = c0 + ty * 4 + q, w = w0 + tx;
            tile[ty * 4 + q][tx] = (w < WW) ? __ldcs(&in[(((size_t)b * 256 + c) * HH + h) * WW + w]) : 0.f;
        }
        __syncthreads();
#pragma unroll
        for (int q = 0; q < 4; q++) {
            int w = w0 + ty * 4 + q;
            if (w >= WW) continue;
            size_t o = ((size_t)b * HW + (size_t)h * WW + w) * 256 + c0 + tx;
            g_bev[o] = __float2half_rn(tile[tx][ty * 4 + q]);
        }
    } else {
        // prep slice: 80 CTAs cover trunk(147456) + hm(36864) + rg(36864)
        const int cta = blockIdx.x + 10 * blockIdx.y;   // 0..79
        for (int i = cta * 256 + threadIdx.x; i < 221184; i += 80 * 256) {
            if (i < 147456)       prep_one(w_sh, g_wimg_sh, 256, i);
            else if (i < 184320)  prep_one(w_hm, g_wimg_hm, 64, i - 147456);
            else                  prep_one(w_rg, g_wimg_rg, 64, i - 184320);
        }
    }
}

// ===========================================================================
// Trunk: conv3x3 (256->64) + BN + ReLU, single-pass fp16 mma, M=32/warp.
// CTA 256 thr (8 warps), tile 16x16 px x 64 oc; warp w = rows 2w, 2w+1.
// Rounds of 3 shifts, double-buffered B; halo staged via cp.async zero-fill.
// (r14 proven config, unchanged)
// ===========================================================================
__global__ __launch_bounds__(256, 2) void trunk_kernel(
    const __half* __restrict__ act, const __half* __restrict__ wimg,
    const float* __restrict__ gg, const float* __restrict__ bbp,
    const float* __restrict__ mm, const float* __restrict__ vv,
    __half* __restrict__ outp)
{
    extern __shared__ __align__(16) unsigned char dynsmem[];
    __half* sB = (__half*)dynsmem;                // 2 bufs x 27648 B = 55296
    __half* s_h = (__half*)(dynsmem + 55296);     // 324 px x 72 (46656 B)

    __shared__ float s_scale[64], s_shift[64];

    const int tid = threadIdx.x;
    const int w = tid >> 5, lane = tid & 31;
    const int bx = blockIdx.x * 16, by = blockIdx.y * 16;
    const int b = blockIdx.z;

    if (tid < 64) {
        float sc = gg[tid] * rsqrtf(vv[tid] + EPSBN);
        s_scale[tid] = sc;
        s_shift[tid] = bbp[tid] - mm[tid] * sc;
    }

    const int mA = lane & 15;
    const int kselA = (lane >> 4) * 8;
    const int oclB = (lane & 7) + ((lane >> 4) & 1) * 8;
    const int koffB = (lane & 8) ? 8 : 0;

    const uint32_t sB_u = smem_u32(sB);
    const uint32_t sh_u = smem_u32(s_h);

    float acc0[8][4], acc1[8][4];
#pragma unroll
    for (int i = 0; i < 8; i++)
#pragma unroll
        for (int j = 0; j < 4; j++) { acc0[i][j] = 0.f; acc1[i][j] = 0.f; }

    // prefetch round 0 (shifts 0..2, contiguous 27648 B)
    for (int i = tid; i < 1728; i += 256)
        CP_ASYNC16(sB_u + i * 16, (const char*)wimg + (size_t)i * 16);
    CP_COMMIT();

#pragma unroll 1
    for (int R = 0; R < 12; R++) {
        if (R % 3 == 0) {
            __syncthreads();   // previous halo readers done
            const int cc = R / 3;
            for (int idx = tid; idx < 324 * 8; idx += 256) {
                int pix = idx >> 3, j = idx & 7;
                int r = pix / 18, col = pix % 18;
                int gy = by - 1 + r, gx = bx - 1 + col;
                bool ok = ((unsigned)gy < HH) && ((unsigned)gx < WW);
                const char* src = (const char*)(act +
                    (ok ? ((size_t)b * HW + (size_t)gy * WW + gx) * 256 + cc * 64 + j * 8
                        : (size_t)0));
                CP_ASYNC16Z(sh_u + (uint32_t)(pix * 144 + j * 16), src, ok ? 16 : 0);
            }
            CP_COMMIT();
        }
        CP_WAIT0();
        __syncthreads();   // B data + halo visible; buf (R+1)&1 readers done
        if (R + 1 < 12) {
            uint32_t dst = sB_u + (uint32_t)((R + 1) & 1) * 27648;
            const char* src = (const char*)wimg + (size_t)(R + 1) * 27648;
            for (int i = tid; i < 1728; i += 256)
                CP_ASYNC16(dst + i * 16, src + (size_t)i * 16);
            CP_COMMIT();
        }

        const uint32_t bufB = sB_u + (uint32_t)(R & 1) * 27648;
#pragma unroll
        for (int q = 0; q < 3; q++) {
            const int k = (R % 3) * 3 + q;
            const int ky = k / 3, kx = k - 3 * ky;
            const uint32_t aBase = sh_u +
                (uint32_t)((((2 * w + ky) * 18 + mA + kx) * 72 + kselA) * 2);
            const uint32_t bBase = bufB + (uint32_t)q * 9216 +
                (uint32_t)((oclB * 72 + koffB) * 2);
#pragma unroll
            for (int kc = 0; kc < 4; kc++) {
                uint32_t a0[4], a1[4];
                ldsm4(a0, aBase + kc * 32);
                ldsm4(a1, aBase + 2592 + kc * 32);   // next row: +18*72*2 B
#pragma unroll
                for (int ng = 0; ng < 4; ng++) {
                    uint32_t bh[4];
                    ldsm4(bh, bBase + ng * 2304 + kc * 32);
                    mma_f16(acc0[2 * ng + 0], a0, bh[0], bh[1]);
                    mma_f16(acc0[2 * ng + 1], a0, bh[2], bh[3]);
                    mma_f16(acc1[2 * ng + 0], a1, bh[0], bh[1]);
                    mma_f16(acc1[2 * ng + 1], a1, bh[2], bh[3]);
                }
            }
        }
    }

    // BN + ReLU -> NHWC fp16 (2 rows per warp)
#pragma unroll
    for (int rr = 0; rr < 2; rr++) {
        const int y = by + 2 * w + rr;
#pragma unroll
        for (int side = 0; side < 2; side++) {
            int x = bx + (lane >> 2) + side * 8;
            if (y < HH && x < WW) {
                size_t base = ((size_t)b * HW + (size_t)y * WW + x) * 64;
#pragma unroll
                for (int nt = 0; nt < 8; nt++) {
                    int oc0 = nt * 8 + (lane & 3) * 2;
                    float v0 = (rr == 0) ? acc0[nt][side * 2 + 0] : acc1[nt][side * 2 + 0];
                    float v1 = (rr == 0) ? acc0[nt][side * 2 + 1] : acc1[nt][side * 2 + 1];
                    v0 = fmaxf(v0 * s_scale[oc0] + s_shift[oc0], 0.f);
                    v1 = fmaxf(v1 * s_scale[oc0 + 1] + s_shift[oc0 + 1], 0.f);
                    __half2 hp;
                    hp.x = __float2half_rn(v0);
                    hp.y = __float2half_rn(v1);
                    *(__half2*)(outp + base + oc0) = hp;
                }
            }
        }
    }
}

// ===========================================================================
// Fused heads, 512 thr / 16 warps = 8 row-pairs x 2 heads.
// Warp (i, j): rows 2i,2i+1 of head j. All 9 shift-pairs resident, but the
// weight burst arrives in 3 progressive commit groups (shifts 0-2/3-5/6-8)
// so compute starts after 55 KB instead of 166 KB.
// ===========================================================================
__global__ __launch_bounds__(512, 1) void heads_kernel(
    const __half* __restrict__ act,
    const __half* __restrict__ wimg_hm, const __half* __restrict__ wimg_rg,
    const float* __restrict__ g1, const float* __restrict__ b1,
    const float* __restrict__ m1, const float* __restrict__ v1,
    const float* __restrict__ g2, const float* __restrict__ b2,
    const float* __restrict__ m2, const float* __restrict__ v2,
    const float* __restrict__ w_hm2, const float* __restrict__ b_hm2,
    const float* __restrict__ w_rg2, const float* __restrict__ b_rg2,
    float* __restrict__ out)
{
    extern __shared__ __align__(16) unsigned char dynsmem[];
    __half* sB = (__half*)dynsmem;                // 9 x (hm 9216 | rg 9216) = 165888 B
    __half* s_h = (__half*)(dynsmem + 165888);    // 324 x 72 (46656 B) -> 212544 total
    float* s_midH = (float*)dynsmem;              // epilogue alias: 256*65*4 = 66560 B
    float* s_midR = (float*)(dynsmem + 66560);    // second buffer (ends 133120 < 165888)

    __shared__ float s_sc1[64], s_sh1[64], s_sc2[64], s_sh2[64];
    __shared__ float s_w2h[3 * 64], s_w2r[8 * 64];
    __shared__ float s_b2h[3], s_b2r[8];

    const int tid = threadIdx.x;
    const int w = tid >> 5, lane = tid & 31;
    const int wi = w & 7;           // row-pair index
    const int wj = w >> 3;          // head index: 0=hm, 1=rg
    const int bx = blockIdx.x * 16, by = blockIdx.y * 16;
    const int b = blockIdx.z;

    if (tid < 64) {
        float sc = g1[tid] * rsqrtf(v1[tid] + EPSBN);
        s_sc1[tid] = sc;
        s_sh1[tid] = b1[tid] - m1[tid] * sc;
        float sc2 = g2[tid] * rsqrtf(v2[tid] + EPSBN);
        s_sc2[tid] = sc2;
        s_sh2[tid] = b2[tid] - m2[tid] * sc2;
    }
    for (int i = tid; i < 192; i += 512) s_w2h[i] = w_hm2[i];
    for (int i = tid; i < 512; i += 512) s_w2r[i] = w_rg2[i];
    if (tid < 3) s_b2h[tid] = b_hm2[tid];
    if (tid < 8) s_b2r[tid] = b_rg2[tid];

    const int mA = lane & 15;
    const int kselA = (lane >> 4) * 8;
    const int oclB = (lane & 7) + ((lane >> 4) & 1) * 8;
    const int koffB = (lane & 8) ? 8 : 0;

    const uint32_t sB_u = smem_u32(sB);
    const uint32_t sh_u = smem_u32(s_h);

    float acc0[8][4], acc1[8][4];   // rows 2wi, 2wi+1 of head wj
#pragma unroll
    for (int i = 0; i < 8; i++)
#pragma unroll
        for (int j = 0; j < 4; j++) { acc0[i][j] = 0.f; acc1[i][j] = 0.f; }

    // weight burst in 3 progressive groups (3 shifts each, hm+rg)
#pragma unroll
    for (int g = 0; g < 3; g++) {
        for (int i = tid; i < 1728; i += 512) {
            int sh3 = i / 576, j = i - sh3 * 576;
            uint32_t dst = sB_u + (uint32_t)(g * 3 + sh3) * 18432 + (uint32_t)j * 16;
            CP_ASYNC16(dst, (const char*)wimg_hm + (size_t)(g * 1728 + i) * 16);
            CP_ASYNC16(dst + 9216, (const char*)wimg_rg + (size_t)(g * 1728 + i) * 16);
        }
        CP_COMMIT();
    }

    // stage halo once (CIN = 64): 324 px, 8 uint4 per pixel (overlaps cp flight)
    for (int idx = tid; idx < 324 * 8; idx += 512) {
        int pix = idx >> 3, j = idx & 7;
        int r = pix / 18, col = pix % 18;
        int gy = by - 1 + r, gx = bx - 1 + col;
        uint4 v = make_uint4(0, 0, 0, 0);
        if ((unsigned)gy < HH && (unsigned)gx < WW)
            v = ((const uint4*)(act + ((size_t)b * HW + (size_t)gy * WW + gx) * 64))[j];
        ((uint4*)(s_h + pix * 72))[j] = v;
    }

    const uint32_t headOff = (uint32_t)wj * 9216;

#pragma unroll 1
    for (int kg = 0; kg < 3; kg++) {
        if (kg == 0) CP_WAIT2();
        else if (kg == 1) CP_WAIT1();
        else CP_WAIT0();
        __syncthreads();

#pragma unroll
        for (int q = 0; q < 3; q++) {
            const int k = kg * 3 + q;
            const int ky = k / 3, kx = k - 3 * ky;
            const uint32_t aBase = sh_u +
                (uint32_t)((((2 * wi + ky) * 18 + mA + kx) * 72 + kselA) * 2);
            const uint32_t bBase = sB_u + (uint32_t)k * 18432 + headOff +
                (uint32_t)((oclB * 72 + koffB) * 2);

#pragma unroll
            for (int kc = 0; kc < 4; kc++) {
                uint32_t a0[4], a1[4];
                ldsm4(a0, aBase + kc * 32);
                ldsm4(a1, aBase + 2592 + kc * 32);
#pragma unroll
                for (int ng = 0; ng < 4; ng++) {
                    uint32_t bh[4];
                    ldsm4(bh, bBase + ng * 2304 + kc * 32);
                    mma_f16(acc0[2 * ng + 0], a0, bh[0], bh[1]);
                    mma_f16(acc0[2 * ng + 1], a0, bh[2], bh[3]);
                    mma_f16(acc1[2 * ng + 0], a1, bh[0], bh[1]);
                    mma_f16(acc1[2 * ng + 1], a1, bh[2], bh[3]);
                }
            }
        }
    }
    __syncthreads();   // all weight/halo reads done; safe to alias s_mid

    // ---- BN + ReLU into this head's mid buffer (rows 2wi, 2wi+1) ----
    {
        const float* sc = wj ? s_sc2 : s_sc1;
        const float* sh = wj ? s_sh2 : s_sh1;
        float* mid = wj ? s_midR : s_midH;
#pragma unroll
        for (int rr = 0; rr < 2; rr++)
#pragma unroll
            for (int side = 0; side < 2; side++) {
                int p = (2 * wi + rr) * 16 + (lane >> 2) + side * 8;
                int oc0 = (lane & 3) * 2;
#pragma unroll
                for (int nt = 0; nt < 8; nt++) {
                    int oc = nt * 8 + oc0;
                    float v0 = (rr == 0) ? acc0[nt][side * 2 + 0] : acc1[nt][side * 2 + 0];
                    float v1 = (rr == 0) ? acc0[nt][side * 2 + 1] : acc1[nt][side * 2 + 1];
                    mid[p * 65 + oc] = fmaxf(v0 * sc[oc] + sh[oc], 0.f);
                    mid[p * 65 + oc + 1] = fmaxf(v1 * sc[oc + 1] + sh[oc + 1], 0.f);
                }
            }
    }
    __syncthreads();

    // ---- parallel 1x1 epilogues: lower half heatmap, upper half box_reg ----
    if (tid < 256) {
        int p = tid;
        int yy = by + (p >> 4), xx = bx + (p & 15);
        if (yy < HH && xx < WW) {
            const float* row = s_midH + p * 65;
            float o0 = s_b2h[0], o1 = s_b2h[1], o2 = s_b2h[2];
#pragma unroll 8
            for (int c = 0; c < 64; c++) {
                float a = row[c];
                o0 += a * s_w2h[c];
                o1 += a * s_w2h[64 + c];
                o2 += a * s_w2h[128 + c];
            }
            size_t base = ((size_t)b * 3 * HH + yy) * WW + xx;
            out[base] = o0;
            out[base + (size_t)HW] = o1;
            out[base + (size_t)2 * HW] = o2;
        }
    } else {
        int p = tid - 256;
        int yy = by + (p >> 4), xx = bx + (p & 15);
        if (yy < HH && xx < WW) {
            const float* row = s_midR + p * 65;
            float o[8];
#pragma unroll
            for (int n = 0; n < 8; n++) o[n] = s_b2r[n];
#pragma unroll 8
            for (int c = 0; c < 64; c++) {
                float a = row[c];
#pragma unroll
                for (int n = 0; n < 8; n++) o[n] += a * s_w2r[n * 64 + c];
            }
            float* rg = out + (size_t)BB * 3 * HW;
#pragma unroll
            for (int n = 0; n < 8; n++)
                rg[((size_t)(b * 8 + n) * HH + yy) * WW + xx] = o[n];
        }
    }
}

// ===========================================================================
extern "C" void kernel_launch(void* const* d_in, const int* in_sizes, int n_in,
                              void* d_out, int out_size)
{
    const float* bev   = (const float*)d_in[0];
    const float* w_sh  = (const float*)d_in[1];
    const float* g_sh  = (const float*)d_in[2];
    const float* b_sh  = (const float*)d_in[3];
    const float* m_sh  = (const float*)d_in[4];
    const float* v_sh  = (const float*)d_in[5];
    const float* w_hm1 = (const float*)d_in[6];
    const float* g_hm1 = (const float*)d_in[7];
    const float* b_hm1 = (const float*)d_in[8];
    const float* m_hm1 = (const float*)d_in[9];
    const float* v_hm1 = (const float*)d_in[10];
    const float* w_hm2 = (const float*)d_in[11];
    const float* b_hm2 = (const float*)d_in[12];
    const float* w_rg1 = (const float*)d_in[13];
    const float* g_rg1 = (const float*)d_in[14];
    const float* b_rg1 = (const float*)d_in[15];
    const float* m_rg1 = (const float*)d_in[16];
    const float* v_rg1 = (const float*)d_in[17];
    const float* w_rg2 = (const float*)d_in[18];
    const float* b_rg2 = (const float*)d_in[19];

    __half *bevh, *trh, *wi_sh, *wi_hm, *wi_rg;
    cudaGetSymbolAddress((void**)&bevh, g_bev);
    cudaGetSymbolAddress((void**)&trh, g_tr);
    cudaGetSymbolAddress((void**)&wi_sh, g_wimg_sh);
    cudaGetSymbolAddress((void**)&wi_hm, g_wimg_hm);
    cudaGetSymbolAddress((void**)&wi_rg, g_wimg_rg);

    const int DSMEM_T = 55296 + 46656;    // 101952 B (occ 2)
    const int DSMEM_H = 165888 + 46656;   // 212544 B (occ 1, 16 warps)
    cudaFuncSetAttribute(trunk_kernel, cudaFuncAttributeMaxDynamicSharedMemorySize, DSMEM_T);
    cudaFuncSetAttribute(heads_kernel, cudaFuncAttributeMaxDynamicSharedMemorySize, DSMEM_H);

    // 1. merged prologue: bev NHWC conversion + all weight images, one launch
    prologue_kernel<<<dim3(10, 8, 1201), 256>>>(bev, w_sh, w_hm1, w_rg1);

    dim3 grid(19, 19, BB);   // 16x16 pixel tiles

    // 2. trunk conv -> NHWC fp16
    trunk_kernel<<<grid, 256, DSMEM_T>>>(bevh, wi_sh, g_sh, b_sh, m_sh, v_sh, trh);

    // 3. fused heads (512 threads, progressive weight arrival) -> d_out
    heads_kernel<<<grid, 512, DSMEM_H>>>(
        trh, wi_hm, wi_rg,
        g_hm1, b_hm1, m_hm1, v_hm1,
        g_rg1, b_rg1, m_rg1, v_rg1,
        w_hm2, b_hm2, w_rg2, b_rg2, (float*)d_out);
}

// round 16
// speedup vs baseline: 2.0774x; 1.0489x over previous
#include <cuda_runtime.h>
#include <cuda_fp16.h>
#include <cstdint>

#define EPSBN 1e-5f
#define HH 300
#define WW 300
#define HW 90000
#define BB 4

// ===========================================================================
// PTX helpers — baseline instructions only (target is sm_103 without 'a')
// ===========================================================================
__device__ __forceinline__ uint32_t smem_u32(const void* p) {
    uint32_t a;
    asm("{ .reg .u64 t; cvta.to.shared.u64 t, %1; cvt.u32.u64 %0, t; }"
        : "=r"(a) : "l"(p));
    return a;
}
__device__ __forceinline__ void ldsm4(uint32_t* r, uint32_t addr) {
    asm volatile("ldmatrix.sync.aligned.m8n8.x4.shared.b16 {%0,%1,%2,%3}, [%4];"
                 : "=r"(r[0]), "=r"(r[1]), "=r"(r[2]), "=r"(r[3]) : "r"(addr));
}
__device__ __forceinline__ void mma_f16(float* c, const uint32_t* a,
                                        uint32_t b0, uint32_t b1) {
    asm volatile(
        "mma.sync.aligned.m16n8k16.row.col.f32.f16.f16.f32 "
        "{%0,%1,%2,%3}, {%4,%5,%6,%7}, {%8,%9}, {%0,%1,%2,%3};"
        : "+f"(c[0]), "+f"(c[1]), "+f"(c[2]), "+f"(c[3])
        : "r"(a[0]), "r"(a[1]), "r"(a[2]), "r"(a[3]), "r"(b0), "r"(b1));
}
#define CP_ASYNC16(dst, src) \
    asm volatile("cp.async.cg.shared.global [%0], [%1], 16;" :: "r"(dst), "l"(src))
#define CP_ASYNC16Z(dst, src, sz) \
    asm volatile("cp.async.cg.shared.global [%0], [%1], 16, %2;" \
                 :: "r"(dst), "l"(src), "r"(sz))
#define CP_COMMIT() asm volatile("cp.async.commit_group;" ::: "memory")
#define CP_WAIT0()  asm volatile("cp.async.wait_group 0;" ::: "memory")
#define CP_WAIT1()  asm volatile("cp.async.wait_group 1;" ::: "memory")
#define CP_WAIT2()  asm volatile("cp.async.wait_group 2;" ::: "memory")

// ===========================================================================
// Device scratch (allocation-guard-safe)
// ===========================================================================
__device__ __half g_bev[(size_t)BB * HW * 256];
__device__ __half g_tr[(size_t)BB * HW * 64];
__device__ __half g_wimg_sh[36 * 4608];  // trunk: 4 cch x 9 shifts, [64 oc][72]
__device__ __half g_wimg_hm[9 * 4608];
__device__ __half g_wimg_rg[9 * 4608];

// ===========================================================================
// Merged prologue: NCHW fp32 -> NHWC fp16 (z < 1200) PLUS all weight-image
// prep (z == 1200 slice) in one launch.
// Conversion tile: 64 c x 32 w per CTA (grid.y = c-block of 4).
// Store phase: warp = one pixel, lane l writes channels {2l,2l+1} as half2
// -> 128 B contiguous per warp-store, minimal index ALU.
// ===========================================================================
__device__ __forceinline__ void prep_one(const float* __restrict__ w,
                                         __half* __restrict__ dst,
                                         int CIN, int i) {
    int kk = i % 9;
    int ci = (i / 9) % CIN;
    int oc = i / (9 * CIN);
    int cc = ci >> 6, c = ci & 63;
    dst[(size_t)(cc * 9 + kk) * 4608 + oc * 72 + c] = __float2half_rn(w[i]);
}

__global__ __launch_bounds__(256) void prologue_kernel(
    const float* __restrict__ in,
    const float* __restrict__ w_sh,
    const float* __restrict__ w_hm,
    const float* __restrict__ w_rg)
{
    __shared__ float tile[64][33];
    if (blockIdx.z < 1200) {
        const int lane = threadIdx.x & 31, wrp = threadIdx.x >> 5;
        const int w0 = blockIdx.x * 32, c0 = blockIdx.y * 64;
        const int b = blockIdx.z / HH, h = blockIdx.z % HH;

        // load 64c x 32w: warp = 8 consecutive channels, lanes span w
        const float* base = in + ((size_t)(b * 256 + c0 + wrp * 8) * HH + h) * WW + w0;
        const bool wok = (w0 + lane) < WW;
#pragma unroll
        for (int q = 0; q < 8; q++)
            tile[wrp * 8 + q][lane] = wok ? __ldcs(base + (size_t)q * HH * WW + lane) : 0.f;
        __syncthreads();

        // store: warp owns pixels wrp*4 .. wrp*4+3; lane -> channels 2l,2l+1
        __half* dst0 = g_bev + ((size_t)b * HW + (size_t)h * WW + w0) * 256 + c0 + 2 * lane;
#pragma unroll
        for (int pq = 0; pq < 4; pq++) {
            int p = wrp * 4 + pq;
            if (w0 + p < WW) {
                __half2 h2;
                h2.x = __float2half_rn(tile[2 * lane][p]);
                h2.y = __float2half_rn(tile[2 * lane + 1][p]);
                *(__half2*)(dst0 + (size_t)p * 256) = h2;
            }
        }
    } else {
        // prep slice: 40 CTAs (x=0..9, y=0..3) cover all weight images
        const int cta = blockIdx.x + 10 * blockIdx.y;   // 0..39
        for (int i = cta * 256 + threadIdx.x; i < 221184; i += 40 * 256) {
            if (i < 147456)       prep_one(w_sh, g_wimg_sh, 256, i);
            else if (i < 184320)  prep_one(w_hm, g_wimg_hm, 64, i - 147456);
            else                  prep_one(w_rg, g_wimg_rg, 64, i - 184320);
        }
    }
}

// ===========================================================================
// Trunk: conv3x3 (256->64) + BN + ReLU, single-pass fp16 mma, M=32/warp.
// CTA 256 thr (8 warps), tile 16x16 px x 64 oc; warp w = rows 2w, 2w+1.
// Rounds of 3 shifts, double-buffered B; halo staged via cp.async zero-fill.
// (r14 proven config, unchanged)
// ===========================================================================
__global__ __launch_bounds__(256, 2) void trunk_kernel(
    const __half* __restrict__ act, const __half* __restrict__ wimg,
    const float* __restrict__ gg, const float* __restrict__ bbp,
    const float* __restrict__ mm, const float* __restrict__ vv,
    __half* __restrict__ outp)
{
    extern __shared__ __align__(16) unsigned char dynsmem[];
    __half* sB = (__half*)dynsmem;                // 2 bufs x 27648 B = 55296
    __half* s_h = (__half*)(dynsmem + 55296);     // 324 px x 72 (46656 B)

    __shared__ float s_scale[64], s_shift[64];

    const int tid = threadIdx.x;
    const int w = tid >> 5, lane = tid & 31;
    const int bx = blockIdx.x * 16, by = blockIdx.y * 16;
    const int b = blockIdx.z;

    if (tid < 64) {
        float sc = gg[tid] * rsqrtf(vv[tid] + EPSBN);
        s_scale[tid] = sc;
        s_shift[tid] = bbp[tid] - mm[tid] * sc;
    }

    const int mA = lane & 15;
    const int kselA = (lane >> 4) * 8;
    const int oclB = (lane & 7) + ((lane >> 4) & 1) * 8;
    const int koffB = (lane & 8) ? 8 : 0;

    const uint32_t sB_u = smem_u32(sB);
    const uint32_t sh_u = smem_u32(s_h);

    float acc0[8][4], acc1[8][4];
#pragma unroll
    for (int i = 0; i < 8; i++)
#pragma unroll
        for (int j = 0; j < 4; j++) { acc0[i][j] = 0.f; acc1[i][j] = 0.f; }

    // prefetch round 0 (shifts 0..2, contiguous 27648 B)
    for (int i = tid; i < 1728; i += 256)
        CP_ASYNC16(sB_u + i * 16, (const char*)wimg + (size_t)i * 16);
    CP_COMMIT();

#pragma unroll 1
    for (int R = 0; R < 12; R++) {
        if (R % 3 == 0) {
            __syncthreads();   // previous halo readers done
            const int cc = R / 3;
            for (int idx = tid; idx < 324 * 8; idx += 256) {
                int pix = idx >> 3, j = idx & 7;
                int r = pix / 18, col = pix % 18;
                int gy = by - 1 + r, gx = bx - 1 + col;
                bool ok = ((unsigned)gy < HH) && ((unsigned)gx < WW);
                const char* src = (const char*)(act +
                    (ok ? ((size_t)b * HW + (size_t)gy * WW + gx) * 256 + cc * 64 + j * 8
                        : (size_t)0));
                CP_ASYNC16Z(sh_u + (uint32_t)(pix * 144 + j * 16), src, ok ? 16 : 0);
            }
            CP_COMMIT();
        }
        CP_WAIT0();
        __syncthreads();   // B data + halo visible; buf (R+1)&1 readers done
        if (R + 1 < 12) {
            uint32_t dst = sB_u + (uint32_t)((R + 1) & 1) * 27648;
            const char* src = (const char*)wimg + (size_t)(R + 1) * 27648;
            for (int i = tid; i < 1728; i += 256)
                CP_ASYNC16(dst + i * 16, src + (size_t)i * 16);
            CP_COMMIT();
        }

        const uint32_t bufB = sB_u + (uint32_t)(R & 1) * 27648;
#pragma unroll
        for (int q = 0; q < 3; q++) {
            const int k = (R % 3) * 3 + q;
            const int ky = k / 3, kx = k - 3 * ky;
            const uint32_t aBase = sh_u +
                (uint32_t)((((2 * w + ky) * 18 + mA + kx) * 72 + kselA) * 2);
            const uint32_t bBase = bufB + (uint32_t)q * 9216 +
                (uint32_t)((oclB * 72 + koffB) * 2);
#pragma unroll
            for (int kc = 0; kc < 4; kc++) {
                uint32_t a0[4], a1[4];
                ldsm4(a0, aBase + kc * 32);
                ldsm4(a1, aBase + 2592 + kc * 32);   // next row: +18*72*2 B
#pragma unroll
                for (int ng = 0; ng < 4; ng++) {
                    uint32_t bh[4];
                    ldsm4(bh, bBase + ng * 2304 + kc * 32);
                    mma_f16(acc0[2 * ng + 0], a0, bh[0], bh[1]);
                    mma_f16(acc0[2 * ng + 1], a0, bh[2], bh[3]);
                    mma_f16(acc1[2 * ng + 0], a1, bh[0], bh[1]);
                    mma_f16(acc1[2 * ng + 1], a1, bh[2], bh[3]);
                }
            }
        }
    }

    // BN + ReLU -> NHWC fp16 (2 rows per warp)
#pragma unroll
    for (int rr = 0; rr < 2; rr++) {
        const int y = by + 2 * w + rr;
#pragma unroll
        for (int side = 0; side < 2; side++) {
            int x = bx + (lane >> 2) + side * 8;
            if (y < HH && x < WW) {
                size_t base = ((size_t)b * HW + (size_t)y * WW + x) * 64;
#pragma unroll
                for (int nt = 0; nt < 8; nt++) {
                    int oc0 = nt * 8 + (lane & 3) * 2;
                    float v0 = (rr == 0) ? acc0[nt][side * 2 + 0] : acc1[nt][side * 2 + 0];
                    float v1 = (rr == 0) ? acc0[nt][side * 2 + 1] : acc1[nt][side * 2 + 1];
                    v0 = fmaxf(v0 * s_scale[oc0] + s_shift[oc0], 0.f);
                    v1 = fmaxf(v1 * s_scale[oc0 + 1] + s_shift[oc0 + 1], 0.f);
                    __half2 hp;
                    hp.x = __float2half_rn(v0);
                    hp.y = __float2half_rn(v1);
                    *(__half2*)(outp + base + oc0) = hp;
                }
            }
        }
    }
}

// ===========================================================================
// Fused heads, 512 thr / 16 warps = 8 row-pairs x 2 heads.
// Warp (i, j): rows 2i,2i+1 of head j. All 9 shift-pairs resident; weights
// arrive in 3 progressive commit groups so compute starts after 55 KB.
// ===========================================================================
__global__ __launch_bounds__(512, 1) void heads_kernel(
    const __half* __restrict__ act,
    const __half* __restrict__ wimg_hm, const __half* __restrict__ wimg_rg,
    const float* __restrict__ g1, const float* __restrict__ b1,
    const float* __restrict__ m1, const float* __restrict__ v1,
    const float* __restrict__ g2, const float* __restrict__ b2,
    const float* __restrict__ m2, const float* __restrict__ v2,
    const float* __restrict__ w_hm2, const float* __restrict__ b_hm2,
    const float* __restrict__ w_rg2, const float* __restrict__ b_rg2,
    float* __restrict__ out)
{
    extern __shared__ __align__(16) unsigned char dynsmem[];
    __half* sB = (__half*)dynsmem;                // 9 x (hm 9216 | rg 9216) = 165888 B
    __half* s_h = (__half*)(dynsmem + 165888);    // 324 x 72 (46656 B) -> 212544 total
    float* s_midH = (float*)dynsmem;              // epilogue alias: 256*65*4 = 66560 B
    float* s_midR = (float*)(dynsmem + 66560);    // second buffer (ends 133120 < 165888)

    __shared__ float s_sc1[64], s_sh1[64], s_sc2[64], s_sh2[64];
    __shared__ float s_w2h[3 * 64], s_w2r[8 * 64];
    __shared__ float s_b2h[3], s_b2r[8];

    const int tid = threadIdx.x;
    const int w = tid >> 5, lane = tid & 31;
    const int wi = w & 7;           // row-pair index
    const int wj = w >> 3;          // head index: 0=hm, 1=rg
    const int bx = blockIdx.x * 16, by = blockIdx.y * 16;
    const int b = blockIdx.z;

    if (tid < 64) {
        float sc = g1[tid] * rsqrtf(v1[tid] + EPSBN);
        s_sc1[tid] = sc;
        s_sh1[tid] = b1[tid] - m1[tid] * sc;
        float sc2 = g2[tid] * rsqrtf(v2[tid] + EPSBN);
        s_sc2[tid] = sc2;
        s_sh2[tid] = b2[tid] - m2[tid] * sc2;
    }
    for (int i = tid; i < 192; i += 512) s_w2h[i] = w_hm2[i];
    for (int i = tid; i < 512; i += 512) s_w2r[i] = w_rg2[i];
    if (tid < 3) s_b2h[tid] = b_hm2[tid];
    if (tid < 8) s_b2r[tid] = b_rg2[tid];

    const int mA = lane & 15;
    const int kselA = (lane >> 4) * 8;
    const int oclB = (lane & 7) + ((lane >> 4) & 1) * 8;
    const int koffB = (lane & 8) ? 8 : 0;

    const uint32_t sB_u = smem_u32(sB);
    const uint32_t sh_u = smem_u32(s_h);

    float acc0[8][4], acc1[8][4];   // rows 2wi, 2wi+1 of head wj
#pragma unroll
    for (int i = 0; i < 8; i++)
#pragma unroll
        for (int j = 0; j < 4; j++) { acc0[i][j] = 0.f; acc1[i][j] = 0.f; }

    // weight burst in 3 progressive groups (3 shifts each, hm+rg)
#pragma unroll
    for (int g = 0; g < 3; g++) {
        for (int i = tid; i < 1728; i += 512) {
            int sh3 = i / 576, j = i - sh3 * 576;
            uint32_t dst = sB_u + (uint32_t)(g * 3 + sh3) * 18432 + (uint32_t)j * 16;
            CP_ASYNC16(dst, (const char*)wimg_hm + (size_t)(g * 1728 + i) * 16);
            CP_ASYNC16(dst + 9216, (const char*)wimg_rg + (size_t)(g * 1728 + i) * 16);
        }
        CP_COMMIT();
    }

    // stage halo once (CIN = 64): 324 px, 8 uint4 per pixel (overlaps cp flight)
    for (int idx = tid; idx < 324 * 8; idx += 512) {
        int pix = idx >> 3, j = idx & 7;
        int r = pix / 18, col = pix % 18;
        int gy = by - 1 + r, gx = bx - 1 + col;
        uint4 v = make_uint4(0, 0, 0, 0);
        if ((unsigned)gy < HH && (unsigned)gx < WW)
            v = ((const uint4*)(act + ((size_t)b * HW + (size_t)gy * WW + gx) * 64))[j];
        ((uint4*)(s_h + pix * 72))[j] = v;
    }

    const uint32_t headOff = (uint32_t)wj * 9216;

#pragma unroll 1
    for (int kg = 0; kg < 3; kg++) {
        if (kg == 0) CP_WAIT2();
        else if (kg == 1) CP_WAIT1();
        else CP_WAIT0();
        __syncthreads();

#pragma unroll
        for (int q = 0; q < 3; q++) {
            const int k = kg * 3 + q;
            const int ky = k / 3, kx = k - 3 * ky;
            const uint32_t aBase = sh_u +
                (uint32_t)((((2 * wi + ky) * 18 + mA + kx) * 72 + kselA) * 2);
            const uint32_t bBase = sB_u + (uint32_t)k * 18432 + headOff +
                (uint32_t)((oclB * 72 + koffB) * 2);

#pragma unroll
            for (int kc = 0; kc < 4; kc++) {
                uint32_t a0[4], a1[4];
                ldsm4(a0, aBase + kc * 32);
                ldsm4(a1, aBase + 2592 + kc * 32);
#pragma unroll
                for (int ng = 0; ng < 4; ng++) {
                    uint32_t bh[4];
                    ldsm4(bh, bBase + ng * 2304 + kc * 32);
                    mma_f16(acc0[2 * ng + 0], a0, bh[0], bh[1]);
                    mma_f16(acc0[2 * ng + 1], a0, bh[2], bh[3]);
                    mma_f16(acc1[2 * ng + 0], a1, bh[0], bh[1]);
                    mma_f16(acc1[2 * ng + 1], a1, bh[2], bh[3]);
                }
            }
        }
    }
    __syncthreads();   // all weight/halo reads done; safe to alias s_mid

    // ---- BN + ReLU into this head's mid buffer (rows 2wi, 2wi+1) ----
    {
        const float* sc = wj ? s_sc2 : s_sc1;
        const float* sh = wj ? s_sh2 : s_sh1;
        float* mid = wj ? s_midR : s_midH;
#pragma unroll
        for (int rr = 0; rr < 2; rr++)
#pragma unroll
            for (int side = 0; side < 2; side++) {
                int p = (2 * wi + rr) * 16 + (lane >> 2) + side * 8;
                int oc0 = (lane & 3) * 2;
#pragma unroll
                for (int nt = 0; nt < 8; nt++) {
                    int oc = nt * 8 + oc0;
                    float v0 = (rr == 0) ? acc0[nt][side * 2 + 0] : acc1[nt][side * 2 + 0];
                    float v1 = (rr == 0) ? acc0[nt][side * 2 + 1] : acc1[nt][side * 2 + 1];
                    mid[p * 65 + oc] = fmaxf(v0 * sc[oc] + sh[oc], 0.f);
                    mid[p * 65 + oc + 1] = fmaxf(v1 * sc[oc + 1] + sh[oc + 1], 0.f);
                }
            }
    }
    __syncthreads();

    // ---- parallel 1x1 epilogues: lower half heatmap, upper half box_reg ----
    if (tid < 256) {
        int p = tid;
        int yy = by + (p >> 4), xx = bx + (p & 15);
        if (yy < HH && xx < WW) {
            const float* row = s_midH + p * 65;
            float o0 = s_b2h[0], o1 = s_b2h[1], o2 = s_b2h[2];
#pragma unroll 8
            for (int c = 0; c < 64; c++) {
                float a = row[c];
                o0 += a * s_w2h[c];
                o1 += a * s_w2h[64 + c];
                o2 += a * s_w2h[128 + c];
            }
            size_t base = ((size_t)b * 3 * HH + yy) * WW + xx;
            out[base] = o0;
            out[base + (size_t)HW] = o1;
            out[base + (size_t)2 * HW] = o2;
        }
    } else {
        int p = tid - 256;
        int yy = by + (p >> 4), xx = bx + (p & 15);
        if (yy < HH && xx < WW) {
            const float* row = s_midR + p * 65;
            float o[8];
#pragma unroll
            for (int n = 0; n < 8; n++) o[n] = s_b2r[n];
#pragma unroll 8
            for (int c = 0; c < 64; c++) {
                float a = row[c];
#pragma unroll
                for (int n = 0; n < 8; n++) o[n] += a * s_w2r[n * 64 + c];
            }
            float* rg = out + (size_t)BB * 3 * HW;
#pragma unroll
            for (int n = 0; n < 8; n++)
                rg[((size_t)(b * 8 + n) * HH + yy) * WW + xx] = o[n];
        }
    }
}

// ===========================================================================
extern "C" void kernel_launch(void* const* d_in, const int* in_sizes, int n_in,
                              void* d_out, int out_size)
{
    const float* bev   = (const float*)d_in[0];
    const float* w_sh  = (const float*)d_in[1];
    const float* g_sh  = (const float*)d_in[2];
    const float* b_sh  = (const float*)d_in[3];
    const float* m_sh  = (const float*)d_in[4];
    const float* v_sh  = (const float*)d_in[5];
    const float* w_hm1 = (const float*)d_in[6];
    const float* g_hm1 = (const float*)d_in[7];
    const float* b_hm1 = (const float*)d_in[8];
    const float* m_hm1 = (const float*)d_in[9];
    const float* v_hm1 = (const float*)d_in[10];
    const float* w_hm2 = (const float*)d_in[11];
    const float* b_hm2 = (const float*)d_in[12];
    const float* w_rg1 = (const float*)d_in[13];
    const float* g_rg1 = (const float*)d_in[14];
    const float* b_rg1 = (const float*)d_in[15];
    const float* m_rg1 = (const float*)d_in[16];
    const float* v_rg1 = (const float*)d_in[17];
    const float* w_rg2 = (const float*)d_in[18];
    const float* b_rg2 = (const float*)d_in[19];

    __half *bevh, *trh, *wi_sh, *wi_hm, *wi_rg;
    cudaGetSymbolAddress((void**)&bevh, g_bev);
    cudaGetSymbolAddress((void**)&trh, g_tr);
    cudaGetSymbolAddress((void**)&wi_sh, g_wimg_sh);
    cudaGetSymbolAddress((void**)&wi_hm, g_wimg_hm);
    cudaGetSymbolAddress((void**)&wi_rg, g_wimg_rg);

    const int DSMEM_T = 55296 + 46656;    // 101952 B (occ 2)
    const int DSMEM_H = 165888 + 46656;   // 212544 B (occ 1, 16 warps)
    cudaFuncSetAttribute(trunk_kernel, cudaFuncAttributeMaxDynamicSharedMemorySize, DSMEM_T);
    cudaFuncSetAttribute(heads_kernel, cudaFuncAttributeMaxDynamicSharedMemorySize, DSMEM_H);

    // 1. merged prologue: bev NHWC conversion (half2 stores) + weight images
    prologue_kernel<<<dim3(10, 4, 1201), 256>>>(bev, w_sh, w_hm1, w_rg1);

    dim3 grid(19, 19, BB);   // 16x16 pixel tiles

    // 2. trunk conv -> NHWC fp16
    trunk_kernel<<<grid, 256, DSMEM_T>>>(bevh, wi_sh, g_sh, b_sh, m_sh, v_sh, trh);

    // 3. fused heads (512 threads, progressive weight arrival) -> d_out
    heads_kernel<<<grid, 512, DSMEM_H>>>(
        trh, wi_hm, wi_rg,
        g_hm1, b_hm1, m_hm1, v_hm1,
        g_rg1, b_rg1, m_rg1, v_rg1,
        w_hm2, b_hm2, w_rg2, b_rg2, (float*)d_out);
}

// round 17
// speedup vs baseline: 2.0791x; 1.0009x over previous
#include <cuda_runtime.h>
#include <cuda_fp16.h>
#include <cstdint>

#define EPSBN 1e-5f
#define HH 300
#define WW 300
#define HW 90000
#define BB 4

// ===========================================================================
// PTX helpers — baseline instructions only (target is sm_103 without 'a')
// ===========================================================================
__device__ __forceinline__ uint32_t smem_u32(const void* p) {
    uint32_t a;
    asm("{ .reg .u64 t; cvta.to.shared.u64 t, %1; cvt.u32.u64 %0, t; }"
        : "=r"(a) : "l"(p));
    return a;
}
__device__ __forceinline__ void ldsm4(uint32_t* r, uint32_t addr) {
    asm volatile("ldmatrix.sync.aligned.m8n8.x4.shared.b16 {%0,%1,%2,%3}, [%4];"
                 : "=r"(r[0]), "=r"(r[1]), "=r"(r[2]), "=r"(r[3]) : "r"(addr));
}
__device__ __forceinline__ void mma_f16(float* c, const uint32_t* a,
                                        uint32_t b0, uint32_t b1) {
    asm volatile(
        "mma.sync.aligned.m16n8k16.row.col.f32.f16.f16.f32 "
        "{%0,%1,%2,%3}, {%4,%5,%6,%7}, {%8,%9}, {%0,%1,%2,%3};"
        : "+f"(c[0]), "+f"(c[1]), "+f"(c[2]), "+f"(c[3])
        : "r"(a[0]), "r"(a[1]), "r"(a[2]), "r"(a[3]), "r"(b0), "r"(b1));
}
#define CP_ASYNC16(dst, src) \
    asm volatile("cp.async.cg.shared.global [%0], [%1], 16;" :: "r"(dst), "l"(src))
#define CP_ASYNC16Z(dst, src, sz) \
    asm volatile("cp.async.cg.shared.global [%0], [%1], 16, %2;" \
                 :: "r"(dst), "l"(src), "r"(sz))
#define CP_COMMIT() asm volatile("cp.async.commit_group;" ::: "memory")
#define CP_WAIT0()  asm volatile("cp.async.wait_group 0;" ::: "memory")
#define CP_WAIT1()  asm volatile("cp.async.wait_group 1;" ::: "memory")
#define CP_WAIT2()  asm volatile("cp.async.wait_group 2;" ::: "memory")

// ===========================================================================
// Device scratch (allocation-guard-safe)
// ===========================================================================
__device__ __half g_bev[(size_t)BB * HW * 256];
__device__ __half g_tr[(size_t)BB * HW * 64];
__device__ __half g_wimg_sh[36 * 4608];  // trunk: 4 cch x 9 shifts, [64 oc][72]
__device__ __half g_wimg_hm[9 * 4608];
__device__ __half g_wimg_rg[9 * 4608];

// ===========================================================================
// Merged prologue: NCHW fp32 -> NHWC fp16 (z < 1200) PLUS all weight-image
// prep (z == 1200 slice) in one launch.
// Conversion tile: 64 c x 32 w. Store: warp = 4 pixels; lane l packs
// channels (l&7)*8..+7 of pixel wrp*4+(l>>3) into ONE uint4 store (512 B
// contiguous per warp store instruction).
// ===========================================================================
__device__ __forceinline__ void prep_one(const float* __restrict__ w,
                                         __half* __restrict__ dst,
                                         int CIN, int i) {
    int kk = i % 9;
    int ci = (i / 9) % CIN;
    int oc = i / (9 * CIN);
    int cc = ci >> 6, c = ci & 63;
    dst[(size_t)(cc * 9 + kk) * 4608 + oc * 72 + c] = __float2half_rn(w[i]);
}

__global__ __launch_bounds__(256) void prologue_kernel(
    const float* __restrict__ in,
    const float* __restrict__ w_sh,
    const float* __restrict__ w_hm,
    const float* __restrict__ w_rg)
{
    __shared__ float tile[64][33];
    if (blockIdx.z < 1200) {
        const int lane = threadIdx.x & 31, wrp = threadIdx.x >> 5;
        const int w0 = blockIdx.x * 32, c0 = blockIdx.y * 64;
        const int b = blockIdx.z / HH, h = blockIdx.z % HH;

        // load 64c x 32w: warp = 8 consecutive channels, lanes span w
        const float* base = in + ((size_t)(b * 256 + c0 + wrp * 8) * HH + h) * WW + w0;
        const bool wok = (w0 + lane) < WW;
#pragma unroll
        for (int q = 0; q < 8; q++)
            tile[wrp * 8 + q][lane] = wok ? __ldcs(base + (size_t)q * HH * WW + lane) : 0.f;
        __syncthreads();

        // store: lane -> pixel wrp*4 + (lane>>3), channels (lane&7)*8..+7
        const int p = wrp * 4 + (lane >> 3);
        const int cg = (lane & 7) * 8;
        if (w0 + p < WW) {
            __half2 h2[4];
#pragma unroll
            for (int q = 0; q < 4; q++) {
                h2[q].x = __float2half_rn(tile[cg + 2 * q][p]);
                h2[q].y = __float2half_rn(tile[cg + 2 * q + 1][p]);
            }
            __half* dst = g_bev + ((size_t)b * HW + (size_t)h * WW + w0 + p) * 256 + c0 + cg;
            *(uint4*)dst = *(uint4*)h2;
        }
    } else {
        // prep slice: 40 CTAs (x=0..9, y=0..3) cover all weight images
        const int cta = blockIdx.x + 10 * blockIdx.y;   // 0..39
        for (int i = cta * 256 + threadIdx.x; i < 221184; i += 40 * 256) {
            if (i < 147456)       prep_one(w_sh, g_wimg_sh, 256, i);
            else if (i < 184320)  prep_one(w_hm, g_wimg_hm, 64, i - 147456);
            else                  prep_one(w_rg, g_wimg_rg, 64, i - 184320);
        }
    }
}

// ===========================================================================
// Trunk: conv3x3 (256->64) + BN + ReLU, single-pass fp16 mma, M=32/warp.
// CTA 256 thr (8 warps), tile 16x16 px x 64 oc; warp w = rows 2w, 2w+1.
// Rounds of 3 shifts, double-buffered B; halo staged via cp.async zero-fill.
// (r14 proven config, unchanged)
// ===========================================================================
__global__ __launch_bounds__(256, 2) void trunk_kernel(
    const __half* __restrict__ act, const __half* __restrict__ wimg,
    const float* __restrict__ gg, const float* __restrict__ bbp,
    const float* __restrict__ mm, const float* __restrict__ vv,
    __half* __restrict__ outp)
{
    extern __shared__ __align__(16) unsigned char dynsmem[];
    __half* sB = (__half*)dynsmem;                // 2 bufs x 27648 B = 55296
    __half* s_h = (__half*)(dynsmem + 55296);     // 324 px x 72 (46656 B)

    __shared__ float s_scale[64], s_shift[64];

    const int tid = threadIdx.x;
    const int w = tid >> 5, lane = tid & 31;
    const int bx = blockIdx.x * 16, by = blockIdx.y * 16;
    const int b = blockIdx.z;

    if (tid < 64) {
        float sc = gg[tid] * rsqrtf(vv[tid] + EPSBN);
        s_scale[tid] = sc;
        s_shift[tid] = bbp[tid] - mm[tid] * sc;
    }

    const int mA = lane & 15;
    const int kselA = (lane >> 4) * 8;
    const int oclB = (lane & 7) + ((lane >> 4) & 1) * 8;
    const int koffB = (lane & 8) ? 8 : 0;

    const uint32_t sB_u = smem_u32(sB);
    const uint32_t sh_u = smem_u32(s_h);

    float acc0[8][4], acc1[8][4];
#pragma unroll
    for (int i = 0; i < 8; i++)
#pragma unroll
        for (int j = 0; j < 4; j++) { acc0[i][j] = 0.f; acc1[i][j] = 0.f; }

    // prefetch round 0 (shifts 0..2, contiguous 27648 B)
    for (int i = tid; i < 1728; i += 256)
        CP_ASYNC16(sB_u + i * 16, (const char*)wimg + (size_t)i * 16);
    CP_COMMIT();

#pragma unroll 1
    for (int R = 0; R < 12; R++) {
        if (R % 3 == 0) {
            __syncthreads();   // previous halo readers done
            const int cc = R / 3;
            for (int idx = tid; idx < 324 * 8; idx += 256) {
                int pix = idx >> 3, j = idx & 7;
                int r = pix / 18, col = pix % 18;
                int gy = by - 1 + r, gx = bx - 1 + col;
                bool ok = ((unsigned)gy < HH) && ((unsigned)gx < WW);
                const char* src = (const char*)(act +
                    (ok ? ((size_t)b * HW + (size_t)gy * WW + gx) * 256 + cc * 64 + j * 8
                        : (size_t)0));
                CP_ASYNC16Z(sh_u + (uint32_t)(pix * 144 + j * 16), src, ok ? 16 : 0);
            }
            CP_COMMIT();
        }
        CP_WAIT0();
        __syncthreads();   // B data + halo visible; buf (R+1)&1 readers done
        if (R + 1 < 12) {
            uint32_t dst = sB_u + (uint32_t)((R + 1) & 1) * 27648;
            const char* src = (const char*)wimg + (size_t)(R + 1) * 27648;
            for (int i = tid; i < 1728; i += 256)
                CP_ASYNC16(dst + i * 16, src + (size_t)i * 16);
            CP_COMMIT();
        }

        const uint32_t bufB = sB_u + (uint32_t)(R & 1) * 27648;
#pragma unroll
        for (int q = 0; q < 3; q++) {
            const int k = (R % 3) * 3 + q;
            const int ky = k / 3, kx = k - 3 * ky;
            const uint32_t aBase = sh_u +
                (uint32_t)((((2 * w + ky) * 18 + mA + kx) * 72 + kselA) * 2);
            const uint32_t bBase = bufB + (uint32_t)q * 9216 +
                (uint32_t)((oclB * 72 + koffB) * 2);
#pragma unroll
            for (int kc = 0; kc < 4; kc++) {
                uint32_t a0[4], a1[4];
                ldsm4(a0, aBase + kc * 32);
                ldsm4(a1, aBase + 2592 + kc * 32);   // next row: +18*72*2 B
#pragma unroll
                for (int ng = 0; ng < 4; ng++) {
                    uint32_t bh[4];
                    ldsm4(bh, bBase + ng * 2304 + kc * 32);
                    mma_f16(acc0[2 * ng + 0], a0, bh[0], bh[1]);
                    mma_f16(acc0[2 * ng + 1], a0, bh[2], bh[3]);
                    mma_f16(acc1[2 * ng + 0], a1, bh[0], bh[1]);
                    mma_f16(acc1[2 * ng + 1], a1, bh[2], bh[3]);
                }
            }
        }
    }

    // BN + ReLU -> NHWC fp16 (2 rows per warp)
#pragma unroll
    for (int rr = 0; rr < 2; rr++) {
        const int y = by + 2 * w + rr;
#pragma unroll
        for (int side = 0; side < 2; side++) {
            int x = bx + (lane >> 2) + side * 8;
            if (y < HH && x < WW) {
                size_t base = ((size_t)b * HW + (size_t)y * WW + x) * 64;
#pragma unroll
                for (int nt = 0; nt < 8; nt++) {
                    int oc0 = nt * 8 + (lane & 3) * 2;
                    float v0 = (rr == 0) ? acc0[nt][side * 2 + 0] : acc1[nt][side * 2 + 0];
                    float v1 = (rr == 0) ? acc0[nt][side * 2 + 1] : acc1[nt][side * 2 + 1];
                    v0 = fmaxf(v0 * s_scale[oc0] + s_shift[oc0], 0.f);
                    v1 = fmaxf(v1 * s_scale[oc0 + 1] + s_shift[oc0 + 1], 0.f);
                    __half2 hp;
                    hp.x = __float2half_rn(v0);
                    hp.y = __float2half_rn(v1);
                    *(__half2*)(outp + base + oc0) = hp;
                }
            }
        }
    }
}

// ===========================================================================
// Fused heads, 512 thr / 16 warps = 8 row-pairs x 2 heads.
// Warp (i, j): rows 2i,2i+1 of head j. All 9 shift-pairs resident; weights
// arrive in 3 progressive commit groups so compute starts after 55 KB.
// ===========================================================================
__global__ __launch_bounds__(512, 1) void heads_kernel(
    const __half* __restrict__ act,
    const __half* __restrict__ wimg_hm, const __half* __restrict__ wimg_rg,
    const float* __restrict__ g1, const float* __restrict__ b1,
    const float* __restrict__ m1, const float* __restrict__ v1,
    const float* __restrict__ g2, const float* __restrict__ b2,
    const float* __restrict__ m2, const float* __restrict__ v2,
    const float* __restrict__ w_hm2, const float* __restrict__ b_hm2,
    const float* __restrict__ w_rg2, const float* __restrict__ b_rg2,
    float* __restrict__ out)
{
    extern __shared__ __align__(16) unsigned char dynsmem[];
    __half* sB = (__half*)dynsmem;                // 9 x (hm 9216 | rg 9216) = 165888 B
    __half* s_h = (__half*)(dynsmem + 165888);    // 324 x 72 (46656 B) -> 212544 total
    float* s_midH = (float*)dynsmem;              // epilogue alias: 256*65*4 = 66560 B
    float* s_midR = (float*)(dynsmem + 66560);    // second buffer (ends 133120 < 165888)

    __shared__ float s_sc1[64], s_sh1[64], s_sc2[64], s_sh2[64];
    __shared__ float s_w2h[3 * 64], s_w2r[8 * 64];
    __shared__ float s_b2h[3], s_b2r[8];

    const int tid = threadIdx.x;
    const int w = tid >> 5, lane = tid & 31;
    const int wi = w & 7;           // row-pair index
    const int wj = w >> 3;          // head index: 0=hm, 1=rg
    const int bx = blockIdx.x * 16, by = blockIdx.y * 16;
    const int b = blockIdx.z;

    if (tid < 64) {
        float sc = g1[tid] * rsqrtf(v1[tid] + EPSBN);
        s_sc1[tid] = sc;
        s_sh1[tid] = b1[tid] - m1[tid] * sc;
        float sc2 = g2[tid] * rsqrtf(v2[tid] + EPSBN);
        s_sc2[tid] = sc2;
        s_sh2[tid] = b2[tid] - m2[tid] * sc2;
    }
    for (int i = tid; i < 192; i += 512) s_w2h[i] = w_hm2[i];
    for (int i = tid; i < 512; i += 512) s_w2r[i] = w_rg2[i];
    if (tid < 3) s_b2h[tid] = b_hm2[tid];
    if (tid < 8) s_b2r[tid] = b_rg2[tid];

    const int mA = lane & 15;
    const int kselA = (lane >> 4) * 8;
    const int oclB = (lane & 7) + ((lane >> 4) & 1) * 8;
    const int koffB = (lane & 8) ? 8 : 0;

    const uint32_t sB_u = smem_u32(sB);
    const uint32_t sh_u = smem_u32(s_h);

    float acc0[8][4], acc1[8][4];   // rows 2wi, 2wi+1 of head wj
#pragma unroll
    for (int i = 0; i < 8; i++)
#pragma unroll
        for (int j = 0; j < 4; j++) { acc0[i][j] = 0.f; acc1[i][j] = 0.f; }

    // weight burst in 3 progressive groups (3 shifts each, hm+rg)
#pragma unroll
    for (int g = 0; g < 3; g++) {
        for (int i = tid; i < 1728; i += 512) {
            int sh3 = i / 576, j = i - sh3 * 576;
            uint32_t dst = sB_u + (uint32_t)(g * 3 + sh3) * 18432 + (uint32_t)j * 16;
            CP_ASYNC16(dst, (const char*)wimg_hm + (size_t)(g * 1728 + i) * 16);
            CP_ASYNC16(dst + 9216, (const char*)wimg_rg + (size_t)(g * 1728 + i) * 16);
        }
        CP_COMMIT();
    }

    // stage halo once (CIN = 64): 324 px, 8 uint4 per pixel (overlaps cp flight)
    for (int idx = tid; idx < 324 * 8; idx += 512) {
        int pix = idx >> 3, j = idx & 7;
        int r = pix / 18, col = pix % 18;
        int gy = by - 1 + r, gx = bx - 1 + col;
        uint4 v = make_uint4(0, 0, 0, 0);
        if ((unsigned)gy < HH && (unsigned)gx < WW)
            v = ((const uint4*)(act + ((size_t)b * HW + (size_t)gy * WW + gx) * 64))[j];
        ((uint4*)(s_h + pix * 72))[j] = v;
    }

    const uint32_t headOff = (uint32_t)wj * 9216;

#pragma unroll 1
    for (int kg = 0; kg < 3; kg++) {
        if (kg == 0) CP_WAIT2();
        else if (kg == 1) CP_WAIT1();
        else CP_WAIT0();
        __syncthreads();

#pragma unroll
        for (int q = 0; q < 3; q++) {
            const int k = kg * 3 + q;
            const int ky = k / 3, kx = k - 3 * ky;
            const uint32_t aBase = sh_u +
                (uint32_t)((((2 * wi + ky) * 18 + mA + kx) * 72 + kselA) * 2);
            const uint32_t bBase = sB_u + (uint32_t)k * 18432 + headOff +
                (uint32_t)((oclB * 72 + koffB) * 2);

#pragma unroll
            for (int kc = 0; kc < 4; kc++) {
                uint32_t a0[4], a1[4];
                ldsm4(a0, aBase + kc * 32);
                ldsm4(a1, aBase + 2592 + kc * 32);
#pragma unroll
                for (int ng = 0; ng < 4; ng++) {
                    uint32_t bh[4];
                    ldsm4(bh, bBase + ng * 2304 + kc * 32);
                    mma_f16(acc0[2 * ng + 0], a0, bh[0], bh[1]);
                    mma_f16(acc0[2 * ng + 1], a0, bh[2], bh[3]);
                    mma_f16(acc1[2 * ng + 0], a1, bh[0], bh[1]);
                    mma_f16(acc1[2 * ng + 1], a1, bh[2], bh[3]);
                }
            }
        }
    }
    __syncthreads();   // all weight/halo reads done; safe to alias s_mid

    // ---- BN + ReLU into this head's mid buffer (rows 2wi, 2wi+1) ----
    {
        const float* sc = wj ? s_sc2 : s_sc1;
        const float* sh = wj ? s_sh2 : s_sh1;
        float* mid = wj ? s_midR : s_midH;
#pragma unroll
        for (int rr = 0; rr < 2; rr++)
#pragma unroll
            for (int side = 0; side < 2; side++) {
                int p = (2 * wi + rr) * 16 + (lane >> 2) + side * 8;
                int oc0 = (lane & 3) * 2;
#pragma unroll
                for (int nt = 0; nt < 8; nt++) {
                    int oc = nt * 8 + oc0;
                    float v0 = (rr == 0) ? acc0[nt][side * 2 + 0] : acc1[nt][side * 2 + 0];
                    float v1 = (rr == 0) ? acc0[nt][side * 2 + 1] : acc1[nt][side * 2 + 1];
                    mid[p * 65 + oc] = fmaxf(v0 * sc[oc] + sh[oc], 0.f);
                    mid[p * 65 + oc + 1] = fmaxf(v1 * sc[oc + 1] + sh[oc + 1], 0.f);
                }
            }
    }
    __syncthreads();

    // ---- parallel 1x1 epilogues: lower half heatmap, upper half box_reg ----
    if (tid < 256) {
        int p = tid;
        int yy = by + (p >> 4), xx = bx + (p & 15);
        if (yy < HH && xx < WW) {
            const float* row = s_midH + p * 65;
            float o0 = s_b2h[0], o1 = s_b2h[1], o2 = s_b2h[2];
#pragma unroll 8
            for (int c = 0; c < 64; c++) {
                float a = row[c];
                o0 += a * s_w2h[c];
                o1 += a * s_w2h[64 + c];
                o2 += a * s_w2h[128 + c];
            }
            size_t base = ((size_t)b * 3 * HH + yy) * WW + xx;
            out[base] = o0;
            out[base + (size_t)HW] = o1;
            out[base + (size_t)2 * HW] = o2;
        }
    } else {
        int p = tid - 256;
        int yy = by + (p >> 4), xx = bx + (p & 15);
        if (yy < HH && xx < WW) {
            const float* row = s_midR + p * 65;
            float o[8];
#pragma unroll
            for (int n = 0; n < 8; n++) o[n] = s_b2r[n];
#pragma unroll 8
            for (int c = 0; c < 64; c++) {
                float a = row[c];
#pragma unroll
                for (int n = 0; n < 8; n++) o[n] += a * s_w2r[n * 64 + c];
            }
            float* rg = out + (size_t)BB * 3 * HW;
#pragma unroll
            for (int n = 0; n < 8; n++)
                rg[((size_t)(b * 8 + n) * HH + yy) * WW + xx] = o[n];
        }
    }
}

// ===========================================================================
extern "C" void kernel_launch(void* const* d_in, const int* in_sizes, int n_in,
                              void* d_out, int out_size)
{
    const float* bev   = (const float*)d_in[0];
    const float* w_sh  = (const float*)d_in[1];
    const float* g_sh  = (const float*)d_in[2];
    const float* b_sh  = (const float*)d_in[3];
    const float* m_sh  = (const float*)d_in[4];
    const float* v_sh  = (const float*)d_in[5];
    const float* w_hm1 = (const float*)d_in[6];
    const float* g_hm1 = (const float*)d_in[7];
    const float* b_hm1 = (const float*)d_in[8];
    const float* m_hm1 = (const float*)d_in[9];
    const float* v_hm1 = (const float*)d_in[10];
    const float* w_hm2 = (const float*)d_in[11];
    const float* b_hm2 = (const float*)d_in[12];
    const float* w_rg1 = (const float*)d_in[13];
    const float* g_rg1 = (const float*)d_in[14];
    const float* b_rg1 = (const float*)d_in[15];
    const float* m_rg1 = (const float*)d_in[16];
    const float* v_rg1 = (const float*)d_in[17];
    const float* w_rg2 = (const float*)d_in[18];
    const float* b_rg2 = (const float*)d_in[19];

    __half *bevh, *trh, *wi_sh, *wi_hm, *wi_rg;
    cudaGetSymbolAddress((void**)&bevh, g_bev);
    cudaGetSymbolAddress((void**)&trh, g_tr);
    cudaGetSymbolAddress((void**)&wi_sh, g_wimg_sh);
    cudaGetSymbolAddress((void**)&wi_hm, g_wimg_hm);
    cudaGetSymbolAddress((void**)&wi_rg, g_wimg_rg);

    const int DSMEM_T = 55296 + 46656;    // 101952 B (occ 2)
    const int DSMEM_H = 165888 + 46656;   // 212544 B (occ 1, 16 warps)
    cudaFuncSetAttribute(trunk_kernel, cudaFuncAttributeMaxDynamicSharedMemorySize, DSMEM_T);
    cudaFuncSetAttribute(heads_kernel, cudaFuncAttributeMaxDynamicSharedMemorySize, DSMEM_H);

    // 1. merged prologue: bev NHWC conversion (uint4 stores) + weight images
    prologue_kernel<<<dim3(10, 4, 1201), 256>>>(bev, w_sh, w_hm1, w_rg1);

    dim3 grid(19, 19, BB);   // 16x16 pixel tiles

    // 2. trunk conv -> NHWC fp16
    trunk_kernel<<<grid, 256, DSMEM_T>>>(bevh, wi_sh, g_sh, b_sh, m_sh, v_sh, trh);

    // 3. fused heads (512 threads, progressive weight arrival) -> d_out
    heads_kernel<<<grid, 512, DSMEM_H>>>(
        trh, wi_hm, wi_rg,
        g_hm1, b_hm1, m_hm1, v_hm1,
        g_rg1, b_rg1, m_rg1, v_rg1,
        w_hm2, b_hm2, w_rg2, b_rg2, (float*)d_out);
}